// round 15
// baseline (speedup 1.0000x reference)
#include <cuda_runtime.h>
#include <cuda_bf16.h>
#include <cstdint>
#include <math.h>

#define NB 8
#define NT 512
#define NC 768
#define NFC 3072
#define NH 12
#define NL 6
#define NDK 64
#define Q_SCALE 0.125f
#define NTP (NT + 2)

// ---------------- scratch ----------------
__device__ float g_x  [NB*NC*NT];
__device__ float g_q  [NB*NC*NT];        // Q only, fp32 [b][C][t]
__device__ float g_y  [NB*NC*NT];
__device__ __nv_bfloat16 g_kb[(size_t)NB*NH*NT*NDK];   // K bf16 [b,h][s][d]
__device__ __nv_bfloat16 g_vb[(size_t)NB*NH*NDK*NT];   // V bf16 [b,h][d][s]

// weights 2-plane per row: [Wh(0..CIN) | Wl(CIN..2CIN)]
__device__ __nv_bfloat16 g_wqkv[(size_t)NL*3*NC*NC*2];
__device__ __nv_bfloat16 g_wo  [(size_t)NL*NC*NC*2];
__device__ __nv_bfloat16 g_w1  [(size_t)NL*3*NFC*NC*2];
__device__ __nv_bfloat16 g_w2  [(size_t)NL*3*NC*NFC*2];
__device__ float         g_bqkv[NL*3*NC];
__device__ __nv_bfloat16 g_bb1[(size_t)NB*NTP*NC*2];
__device__ __nv_bfloat16 g_bb2[(size_t)NB*NTP*NFC*2];

__device__ __forceinline__ void split2(float v, __nv_bfloat16& hi, __nv_bfloat16& lo) {
    hi = __float2bfloat16_rn(v);
    lo = __float2bfloat16_rn(v - __bfloat162float(hi));
}

__device__ __forceinline__ float fexp(float x) {
    float y = x * 1.4426950408889634f;
    float n = rintf(y);
    float f = y - n;
    float p = 0.0013333558146428443f;
    p = fmaf(p, f, 0.009618129107628477f);
    p = fmaf(p, f, 0.05550410866482158f);
    p = fmaf(p, f, 0.2402265069591007f);
    p = fmaf(p, f, 0.6931471805599453f);
    p = fmaf(p, f, 1.0f);
    return __int_as_float(__float_as_int(p) + (((int)n) << 23));
}

// ================= conversions (2-plane weights) =================
__global__ void convert_small(const float* __restrict__ Wq, const float* __restrict__ Wk,
                              const float* __restrict__ Wv, const float* __restrict__ Wo,
                              __nv_bfloat16* __restrict__ oq, __nv_bfloat16* __restrict__ oo, int n) {
    int idx = blockIdx.x * 256 + threadIdx.x;
    if (idx >= n) return;
    int c = idx % NC;
    int m = (idx / NC) % NC;
    int l = idx / (NC * NC);
    const int KP2 = 2 * NC;
    float vals[3] = { Wq[idx] * Q_SCALE, Wk[idx], Wv[idx] };
    size_t lb = (size_t)l * (3*NC) * KP2;
    #pragma unroll
    for (int s = 0; s < 3; s++) {
        __nv_bfloat16 hi, lo; split2(vals[s], hi, lo);
        size_t base = lb + (size_t)(s * NC + m) * KP2;
        oq[base + c] = hi; oq[base + NC + c] = lo;
    }
    __nv_bfloat16 hi, lo; split2(Wo[idx], hi, lo);
    size_t base = ((size_t)l * NC + m) * KP2;
    oo[base + c] = hi; oo[base + NC + c] = lo;
}

__global__ void convert_w_tap(const float* __restrict__ w, __nv_bfloat16* __restrict__ o,
                              int M, int CIN, int n8) {
    int idx = blockIdx.x * 256 + threadIdx.x;
    if (idx >= n8) return;                     // n8 = NL*3*M*(CIN/8)
    int k  = idx % 3;
    int c8 = (idx / 3) % (CIN / 8);
    int m  = (idx / 3 / (CIN / 8)) % M;
    int l  = idx / 3 / (CIN / 8) / M;
    const float* src = w + (((size_t)((size_t)l * M + m) * CIN + c8 * 8) * 3 + k);
    __nv_bfloat16 hb[8], lb[8];
    #pragma unroll
    for (int j = 0; j < 8; j++) split2(src[j * 3], hb[j], lb[j]);
    size_t p = ((size_t)(l * 3 + k) * M + m) * (size_t)(2 * CIN) + c8 * 8;
    *(uint4*)(o + p)       = *(uint4*)hb;
    *(uint4*)(o + p + CIN) = *(uint4*)lb;
}

__global__ void misc_init(const float* __restrict__ x, const float* __restrict__ msk,
                          const float* __restrict__ bq, const float* __restrict__ bk,
                          const float* __restrict__ bv) {
    int idx = blockIdx.x * 256 + threadIdx.x;
    const int N0 = NB*NC*NT;
    if (idx < N0) {
        int t = idx % NT, b = idx / (NC*NT);
        g_x[idx] = x[idx] * msk[b*NT + t];
        return;
    }
    idx -= N0;
    const int N1 = NL*3*NC;
    if (idx < N1) {
        int j = idx % (3*NC), l = idx / (3*NC);
        g_bqkv[idx] = (j < NC) ? bq[l*NC + j] * Q_SCALE
                    : (j < 2*NC) ? bk[l*NC + j - NC] : bv[l*NC + j - 2*NC];
        return;
    }
    idx -= N1;
    const int N2 = NB*2*(2*NC);
    if (idx < N2) {
        int b = idx / (2*2*NC), r = (idx / (2*NC)) & 1, c = idx % (2*NC);
        g_bb1[((size_t)b*NTP + (r ? NT+1 : 0)) * (2*NC) + c] = __float2bfloat16(0.f);
        return;
    }
    idx -= N2;
    const int N3 = NB*2*(2*NFC);
    if (idx < N3) {
        int b = idx / (2*2*NFC), r = (idx / (2*NFC)) & 1, c = idx % (2*NFC);
        g_bb2[((size_t)b*NTP + (r ? NT+1 : 0)) * (2*NFC) + c] = __float2bfloat16(0.f);
    }
}

__global__ void __launch_bounds__(256) im2col_pad(const float* __restrict__ act,
                                                  __nv_bfloat16* __restrict__ bp, int CIN) {
    __shared__ float tile[32][33];
    const int c0 = blockIdx.x * 32, t00 = blockIdx.y * 32, b = blockIdx.z;
    #pragma unroll
    for (int i = 0; i < 4; i++) {
        int idx = threadIdx.x + i * 256;
        int cl = idx >> 5, tl = idx & 31;
        tile[cl][tl] = act[((size_t)b * CIN + c0 + cl) * NT + t00 + tl];
    }
    __syncthreads();
    #pragma unroll
    for (int i = 0; i < 4; i++) {
        int idx = threadIdx.x + i * 256;
        int tl = idx >> 5, cl = idx & 31;
        __nv_bfloat16 hi, lo; split2(tile[cl][tl], hi, lo);
        size_t row = ((size_t)b * NTP + 1 + t00 + tl) * (2*CIN);
        bp[row + c0 + cl] = hi;
        bp[row + CIN + c0 + cl] = lo;
    }
}

// ================= mma.sync primitives =================
__device__ __forceinline__ uint32_t smem_u32(const void* p) {
    uint32_t a;
    asm("{ .reg .u64 t; cvta.to.shared.u64 t, %1; cvt.u32.u64 %0, t; }" : "=r"(a) : "l"(p));
    return a;
}
#define CP_ASYNC16(dst, src) asm volatile("cp.async.cg.shared.global [%0], [%1], 16;" :: "r"(dst), "l"(src))
#define CP_COMMIT()          asm volatile("cp.async.commit_group;" ::: "memory")
#define CP_WAIT1()           asm volatile("cp.async.wait_group 1;" ::: "memory")
#define CP_WAIT0()           asm volatile("cp.async.wait_group 0;" ::: "memory")

__device__ __forceinline__ void ldsm_x4(uint32_t& r0, uint32_t& r1, uint32_t& r2, uint32_t& r3, uint32_t a) {
    asm volatile("ldmatrix.sync.aligned.m8n8.x4.shared.b16 {%0,%1,%2,%3}, [%4];"
        : "=r"(r0), "=r"(r1), "=r"(r2), "=r"(r3) : "r"(a));
}
__device__ __forceinline__ void mma16816(float* d, uint32_t a0, uint32_t a1, uint32_t a2, uint32_t a3,
                                         uint32_t b0, uint32_t b1) {
    asm volatile("mma.sync.aligned.m16n8k16.row.col.f32.bf16.bf16.f32 "
        "{%0,%1,%2,%3}, {%4,%5,%6,%7}, {%8,%9}, {%0,%1,%2,%3};"
        : "+f"(d[0]), "+f"(d[1]), "+f"(d[2]), "+f"(d[3])
        : "r"(a0), "r"(a1), "r"(a2), "r"(a3), "r"(b0), "r"(b1));
}

// ---------------- 128m x 128t tile, 3 products per staged 32-k chunk ----------------
// Stage rows (128B): A[m] = [Wh32|Wl32], B[t] = [Xh32|Xl32]. Products:
// P1=Ah*BXh, P2=Al*BXh, P3=Ah*BXl  (BXh held in regs across A loads).
template<int MTOT, int CIN, int TAPS, bool RELU, bool BB2, bool QKV>
__global__ void __launch_bounds__(256, 2) mma_gemm(
    const __nv_bfloat16* __restrict__ Aw, const float* __restrict__ bias,
    const __nv_bfloat16* __restrict__ Bb, void* __restrict__ outp,
    __nv_bfloat16* __restrict__ kb, __nv_bfloat16* __restrict__ vb)
{
    constexpr int KP2 = CIN * 2;
    constexpr int NKC = CIN / 32;
    constexpr int TOT = NKC * TAPS;
    constexpr int OFF0 = (TAPS == 1) ? 1 : 0;

    extern __shared__ __align__(1024) char smem[];   // 3 stages x (A 16KB | B 16KB)
    const uint32_t sbase = smem_u32(smem);
    const int tid = threadIdx.x;
    const int wid = tid >> 5, lane = tid & 31;
    const int m0 = blockIdx.x * 128;
    const int t0 = blockIdx.y * 128;
    const int b  = blockIdx.z;

    const __nv_bfloat16* Ag = Aw + (size_t)m0 * KP2;
    const __nv_bfloat16* Bg = Bb + ((size_t)b * NTP + t0 + OFF0) * KP2;

    const int wm = (wid >> 1) * 32;
    const int wn = (wid & 1) * 64;

    float acc[2][8][4];
    #pragma unroll
    for (int i = 0; i < 2; i++)
        #pragma unroll
        for (int j = 0; j < 8; j++)
            #pragma unroll
            for (int q = 0; q < 4; q++) acc[i][j][q] = 0.f;

    auto stage_off = [&](int st) { return sbase + st * 32768u; };

    #define LOAD_STAGE(ST, IC) do { \
        const int _tap = (TAPS == 1) ? 0 : ((IC) / NKC); \
        const int _kc  = ((IC) - _tap * NKC) * 32; \
        uint32_t sa = stage_off(ST); \
        const __nv_bfloat16* _Asrc = Ag + (size_t)_tap * MTOT * KP2; \
        const __nv_bfloat16* _Bsrc = Bg + (size_t)_tap * KP2; \
        _Pragma("unroll") \
        for (int it = 0; it < 8; it++) { \
            int idx = tid + it * 256; \
            if (idx < 1024) { \
                int r = idx >> 3, c = idx & 7; \
                CP_ASYNC16(sa + r * 128 + ((c ^ (r & 7)) * 16), \
                           _Asrc + (size_t)r * KP2 + (c >> 2) * CIN + _kc + (c & 3) * 8); \
            } else { \
                int j2 = idx - 1024; int r = j2 >> 3, c = j2 & 7; \
                CP_ASYNC16(sa + 16384 + r * 128 + ((c ^ (r & 7)) * 16), \
                           _Bsrc + (size_t)r * KP2 + (c >> 2) * CIN + _kc + (c & 3) * 8); \
            } \
        } \
    } while (0)

    LOAD_STAGE(0, 0);
    CP_COMMIT();
    LOAD_STAGE(1, 1);
    CP_COMMIT();

    for (int ic = 0; ic < TOT; ic++) {
        CP_WAIT1();
        __syncthreads();
        if (ic + 2 < TOT) {
            int st = (ic + 2) % 3;
            LOAD_STAGE(st, ic + 2);
            CP_COMMIT();
        }

        const uint32_t sA = stage_off(ic % 3);
        const uint32_t sB = sA + 16384;

        #pragma unroll
        for (int kk = 0; kk < 2; kk++) {
            const int cB = kk * 2 + ((lane >> 3) & 1);   // Xh chunk col (0..3)
            const int cA = kk * 2 + (lane >> 4);         // Wh chunk col (0..3)

            uint32_t bf[8][2];
            #pragma unroll
            for (int nf4 = 0; nf4 < 4; nf4++) {          // BXh
                int r = wn + nf4 * 16 + (lane & 7) + ((lane >> 4) & 1) * 8;
                uint32_t r0, r1, r2, r3;
                ldsm_x4(r0, r1, r2, r3, sB + r * 128 + ((cB ^ (r & 7)) * 16));
                bf[nf4*2][0] = r0; bf[nf4*2][1] = r1;
                bf[nf4*2+1][0] = r2; bf[nf4*2+1][1] = r3;
            }
            uint32_t a[2][4];
            #pragma unroll
            for (int mf = 0; mf < 2; mf++) {             // Ah
                int r = wm + mf * 16 + (lane & 15);
                ldsm_x4(a[mf][0], a[mf][1], a[mf][2], a[mf][3],
                        sA + r * 128 + ((cA ^ (r & 7)) * 16));
            }
            #pragma unroll
            for (int mf = 0; mf < 2; mf++)               // P1 = Ah*BXh
                #pragma unroll
                for (int nf = 0; nf < 8; nf++)
                    mma16816(acc[mf][nf], a[mf][0], a[mf][1], a[mf][2], a[mf][3],
                             bf[nf][0], bf[nf][1]);
            #pragma unroll
            for (int mf = 0; mf < 2; mf++) {             // Al
                int r = wm + mf * 16 + (lane & 15);
                ldsm_x4(a[mf][0], a[mf][1], a[mf][2], a[mf][3],
                        sA + r * 128 + (((cA + 4) ^ (r & 7)) * 16));
            }
            #pragma unroll
            for (int mf = 0; mf < 2; mf++)               // P2 = Al*BXh
                #pragma unroll
                for (int nf = 0; nf < 8; nf++)
                    mma16816(acc[mf][nf], a[mf][0], a[mf][1], a[mf][2], a[mf][3],
                             bf[nf][0], bf[nf][1]);
            #pragma unroll
            for (int nf4 = 0; nf4 < 4; nf4++) {          // BXl
                int r = wn + nf4 * 16 + (lane & 7) + ((lane >> 4) & 1) * 8;
                uint32_t r0, r1, r2, r3;
                ldsm_x4(r0, r1, r2, r3, sB + r * 128 + (((cB + 4) ^ (r & 7)) * 16));
                bf[nf4*2][0] = r0; bf[nf4*2][1] = r1;
                bf[nf4*2+1][0] = r2; bf[nf4*2+1][1] = r3;
            }
            #pragma unroll
            for (int mf = 0; mf < 2; mf++) {             // Ah reload
                int r = wm + mf * 16 + (lane & 15);
                ldsm_x4(a[mf][0], a[mf][1], a[mf][2], a[mf][3],
                        sA + r * 128 + ((cA ^ (r & 7)) * 16));
            }
            #pragma unroll
            for (int mf = 0; mf < 2; mf++)               // P3 = Ah*BXl
                #pragma unroll
                for (int nf = 0; nf < 8; nf++)
                    mma16816(acc[mf][nf], a[mf][0], a[mf][1], a[mf][2], a[mf][3],
                             bf[nf][0], bf[nf][1]);
        }
    }
    #undef LOAD_STAGE

    const int gr = lane >> 2, qc = lane & 3;
    #pragma unroll
    for (int mf = 0; mf < 2; mf++) {
        int mA = m0 + wm + mf * 16 + gr;
        int mB = mA + 8;
        float bsA = bias[mA], bsB = bias[mB];
        #pragma unroll
        for (int nf = 0; nf < 8; nf++) {
            int tc = wn + nf * 8 + qc * 2;
            float v0 = acc[mf][nf][0] + bsA, v1 = acc[mf][nf][1] + bsA;
            float v2 = acc[mf][nf][2] + bsB, v3 = acc[mf][nf][3] + bsB;
            if (RELU) { v0 = fmaxf(v0,0.f); v1 = fmaxf(v1,0.f); v2 = fmaxf(v2,0.f); v3 = fmaxf(v3,0.f); }
            if (BB2) {
                __nv_bfloat16* bb = (__nv_bfloat16*)outp;
                size_t r0w = ((size_t)b*NTP + 1 + t0 + tc) * (2*MTOT);
                size_t r1w = r0w + (2*MTOT);
                __nv_bfloat16 h, l;
                split2(v0, h, l); bb[r0w + mA] = h; bb[r0w + MTOT + mA] = l;
                split2(v1, h, l); bb[r1w + mA] = h; bb[r1w + MTOT + mA] = l;
                split2(v2, h, l); bb[r0w + mB] = h; bb[r0w + MTOT + mB] = l;
                split2(v3, h, l); bb[r1w + mB] = h; bb[r1w + MTOT + mB] = l;
            } else if (QKV && m0 >= NC) {
                const bool isK = (m0 < 2*NC);
                int moff = mA - (isK ? NC : 2*NC);
                int hh = moff >> 6, dA = moff & 63;
                int st = t0 + tc;
                if (isK) {
                    __nv_bfloat16* kp = kb + ((size_t)b*NH + hh) * NT * NDK;
                    kp[(size_t)st*NDK + dA]         = __float2bfloat16_rn(v0);
                    kp[(size_t)(st+1)*NDK + dA]     = __float2bfloat16_rn(v1);
                    kp[(size_t)st*NDK + dA + 8]     = __float2bfloat16_rn(v2);
                    kp[(size_t)(st+1)*NDK + dA + 8] = __float2bfloat16_rn(v3);
                } else {
                    __nv_bfloat16* vp = vb + ((size_t)b*NH + hh) * NDK * NT;
                    *(__nv_bfloat162*)(vp + (size_t)dA*NT + st)     = __nv_bfloat162{__float2bfloat16_rn(v0), __float2bfloat16_rn(v1)};
                    *(__nv_bfloat162*)(vp + (size_t)(dA+8)*NT + st) = __nv_bfloat162{__float2bfloat16_rn(v2), __float2bfloat16_rn(v3)};
                }
            } else {
                const int MST = QKV ? NC : MTOT;
                float* out = (float*)outp;
                float* rowA = out + ((size_t)b * MST + mA) * NT + t0;
                float* rowB = out + ((size_t)b * MST + mB) * NT + t0;
                *(float2*)(rowA + tc) = make_float2(v0, v1);
                *(float2*)(rowB + tc) = make_float2(v2, v3);
            }
        }
    }
}

// ---------------- 128m x 64t tile, 3 CTAs/SM, same 3-product scheme ----------------
template<int MTOT, int CIN, int TAPS>
__global__ void __launch_bounds__(256, 3) mma_gemm_t64(
    const __nv_bfloat16* __restrict__ Aw, const float* __restrict__ bias,
    const __nv_bfloat16* __restrict__ Bb, float* __restrict__ out)
{
    constexpr int KP2 = CIN * 2;
    constexpr int NKC = CIN / 32;
    constexpr int TOT = NKC * TAPS;
    constexpr int OFF0 = (TAPS == 1) ? 1 : 0;

    extern __shared__ __align__(1024) char smem[];   // 3 stages x (A 16KB | B 8KB)
    const uint32_t sbase = smem_u32(smem);
    const int tid = threadIdx.x;
    const int wid = tid >> 5, lane = tid & 31;
    const int m0 = blockIdx.x * 128;
    const int t0 = blockIdx.y * 64;
    const int b  = blockIdx.z;

    const __nv_bfloat16* Ag = Aw + (size_t)m0 * KP2;
    const __nv_bfloat16* Bg = Bb + ((size_t)b * NTP + t0 + OFF0) * KP2;

    const int wm = (wid >> 1) * 32;
    const int wn = (wid & 1) * 32;

    float acc[2][4][4];
    #pragma unroll
    for (int i = 0; i < 2; i++)
        #pragma unroll
        for (int j = 0; j < 4; j++)
            #pragma unroll
            for (int q = 0; q < 4; q++) acc[i][j][q] = 0.f;

    auto stage_off = [&](int st) { return sbase + st * 24576u; };

    #define LOAD_STAGE64(ST, IC) do { \
        const int _tap = (TAPS == 1) ? 0 : ((IC) / NKC); \
        const int _kc  = ((IC) - _tap * NKC) * 32; \
        uint32_t sa = stage_off(ST); \
        const __nv_bfloat16* _Asrc = Ag + (size_t)_tap * MTOT * KP2; \
        const __nv_bfloat16* _Bsrc = Bg + (size_t)_tap * KP2; \
        _Pragma("unroll") \
        for (int it = 0; it < 6; it++) { \
            int idx = tid + it * 256; \
            if (idx < 1024) { \
                int r = idx >> 3, c = idx & 7; \
                CP_ASYNC16(sa + r * 128 + ((c ^ (r & 7)) * 16), \
                           _Asrc + (size_t)r * KP2 + (c >> 2) * CIN + _kc + (c & 3) * 8); \
            } else { \
                int j2 = idx - 1024; int r = j2 >> 3, c = j2 & 7; \
                CP_ASYNC16(sa + 16384 + r * 128 + ((c ^ (r & 7)) * 16), \
                           _Bsrc + (size_t)r * KP2 + (c >> 2) * CIN + _kc + (c & 3) * 8); \
            } \
        } \
    } while (0)

    LOAD_STAGE64(0, 0);
    CP_COMMIT();
    LOAD_STAGE64(1, 1);
    CP_COMMIT();

    for (int ic = 0; ic < TOT; ic++) {
        CP_WAIT1();
        __syncthreads();
        if (ic + 2 < TOT) {
            int st = (ic + 2) % 3;
            LOAD_STAGE64(st, ic + 2);
            CP_COMMIT();
        }

        const uint32_t sA = stage_off(ic % 3);
        const uint32_t sB = sA + 16384;

        #pragma unroll
        for (int kk = 0; kk < 2; kk++) {
            const int cB = kk * 2 + ((lane >> 3) & 1);
            const int cA = kk * 2 + (lane >> 4);

            uint32_t bf[4][2];
            #pragma unroll
            for (int nf4 = 0; nf4 < 2; nf4++) {          // BXh
                int r = wn + nf4 * 16 + (lane & 7) + ((lane >> 4) & 1) * 8;
                uint32_t r0, r1, r2, r3;
                ldsm_x4(r0, r1, r2, r3, sB + r * 128 + ((cB ^ (r & 7)) * 16));
                bf[nf4*2][0] = r0; bf[nf4*2][1] = r1;
                bf[nf4*2+1][0] = r2; bf[nf4*2+1][1] = r3;
            }
            uint32_t a[2][4];
            #pragma unroll
            for (int mf = 0; mf < 2; mf++) {             // Ah
                int r = wm + mf * 16 + (lane & 15);
                ldsm_x4(a[mf][0], a[mf][1], a[mf][2], a[mf][3],
                        sA + r * 128 + ((cA ^ (r & 7)) * 16));
            }
            #pragma unroll
            for (int mf = 0; mf < 2; mf++)
                #pragma unroll
                for (int nf = 0; nf < 4; nf++)
                    mma16816(acc[mf][nf], a[mf][0], a[mf][1], a[mf][2], a[mf][3],
                             bf[nf][0], bf[nf][1]);
            #pragma unroll
            for (int mf = 0; mf < 2; mf++) {             // Al
                int r = wm + mf * 16 + (lane & 15);
                ldsm_x4(a[mf][0], a[mf][1], a[mf][2], a[mf][3],
                        sA + r * 128 + (((cA + 4) ^ (r & 7)) * 16));
            }
            #pragma unroll
            for (int mf = 0; mf < 2; mf++)
                #pragma unroll
                for (int nf = 0; nf < 4; nf++)
                    mma16816(acc[mf][nf], a[mf][0], a[mf][1], a[mf][2], a[mf][3],
                             bf[nf][0], bf[nf][1]);
            #pragma unroll
            for (int nf4 = 0; nf4 < 2; nf4++) {          // BXl
                int r = wn + nf4 * 16 + (lane & 7) + ((lane >> 4) & 1) * 8;
                uint32_t r0, r1, r2, r3;
                ldsm_x4(r0, r1, r2, r3, sB + r * 128 + (((cB + 4) ^ (r & 7)) * 16));
                bf[nf4*2][0] = r0; bf[nf4*2][1] = r1;
                bf[nf4*2+1][0] = r2; bf[nf4*2+1][1] = r3;
            }
            #pragma unroll
            for (int mf = 0; mf < 2; mf++) {             // Ah reload
                int r = wm + mf * 16 + (lane & 15);
                ldsm_x4(a[mf][0], a[mf][1], a[mf][2], a[mf][3],
                        sA + r * 128 + ((cA ^ (r & 7)) * 16));
            }
            #pragma unroll
            for (int mf = 0; mf < 2; mf++)
                #pragma unroll
                for (int nf = 0; nf < 4; nf++)
                    mma16816(acc[mf][nf], a[mf][0], a[mf][1], a[mf][2], a[mf][3],
                             bf[nf][0], bf[nf][1]);
        }
    }
    #undef LOAD_STAGE64

    const int gr = lane >> 2, qc = lane & 3;
    #pragma unroll
    for (int mf = 0; mf < 2; mf++) {
        int mA = m0 + wm + mf * 16 + gr;
        int mB = mA + 8;
        float bsA = bias[mA], bsB = bias[mB];
        float* rowA = out + ((size_t)b * MTOT + mA) * NT + t0;
        float* rowB = out + ((size_t)b * MTOT + mB) * NT + t0;
        #pragma unroll
        for (int nf = 0; nf < 4; nf++) {
            int tc = wn + nf * 8 + qc * 2;
            *(float2*)(rowA + tc) = make_float2(acc[mf][nf][0] + bsA, acc[mf][nf][1] + bsA);
            *(float2*)(rowB + tc) = make_float2(acc[mf][nf][2] + bsB, acc[mf][nf][3] + bsB);
        }
    }
}

// ================= tensor-core attention (2 CTAs/SM, cp.async K/V) =================
#define ASM_S   0u
#define ASM_KV  66560u
#define ASM_Q   99328u
#define ASM_RQ  107520u
#define ASM_TOT (107520 + 32*12*4)

__global__ void __launch_bounds__(256, 2) attn_kernel(const float* __restrict__ relk,
                                                      const float* __restrict__ relv,
                                                      __nv_bfloat16* __restrict__ bbo) {
    extern __shared__ __align__(1024) char smraw[];
    const uint32_t sb = smem_u32(smraw);
    float* S  = (float*)(smraw + ASM_S);
    float* rq = (float*)(smraw + ASM_RQ);

    const int tid = threadIdx.x;
    const int wid = tid >> 5, lane = tid & 31;
    const int b = blockIdx.z, h = blockIdx.y;
    const int tq0 = blockIdx.x * 32;
    const float* qg = g_q + ((size_t)b*NC + h*NDK) * NT;
    const __nv_bfloat16* kbp = g_kb + ((size_t)b*NH + h) * NT * NDK;
    const __nv_bfloat16* vbp = g_vb + ((size_t)b*NH + h) * NDK * NT;

    #pragma unroll
    for (int i = 0; i < 8; i++) {
        int idx = tid + i * 256;
        int t = idx & 31, d = idx >> 5;
        float v = qg[(size_t)d*NT + tq0 + t];
        __nv_bfloat16 hi, lo; split2(v, hi, lo);
        uint32_t off = (uint32_t)t*128 + ((((uint32_t)d>>3) ^ (t&7))*16) + (d&7)*2;
        *(__nv_bfloat16*)(smraw + ASM_Q + off)        = hi;
        *(__nv_bfloat16*)(smraw + ASM_Q + 4096 + off) = lo;
    }
    for (int idx = tid; idx < 32*9; idx += 256) {
        int t = idx / 9, dd = idx % 9;
        float s = 0.f;
        #pragma unroll
        for (int d = 0; d < 64; d++) s += qg[(size_t)d*NT + tq0 + t] * relk[dd*64 + d];
        rq[t*12 + dd] = s;
    }
    __syncthreads();

    #pragma unroll
    for (int half = 0; half < 2; half++) {
        #pragma unroll
        for (int i = 0; i < 8; i++) {
            int ch = tid + i * 256;
            int s = ch >> 3, c16 = ch & 7;
            CP_ASYNC16(sb + ASM_KV + (uint32_t)s*128 + (((uint32_t)c16 ^ (s&7))*16),
                       kbp + ((size_t)(half*256 + s))*NDK + c16*8);
        }
        CP_COMMIT(); CP_WAIT0();
        __syncthreads();

        float acc[2][4][4];
        #pragma unroll
        for (int i = 0; i < 2; i++)
            #pragma unroll
            for (int j = 0; j < 4; j++)
                #pragma unroll
                for (int q = 0; q < 4; q++) acc[i][j][q] = 0.f;

        #pragma unroll
        for (int pass = 0; pass < 2; pass++) {
            const uint32_t sA = sb + ASM_Q + pass * 4096;
            #pragma unroll
            for (int k16 = 0; k16 < 4; k16++) {
                uint32_t a[2][4];
                #pragma unroll
                for (int mf = 0; mf < 2; mf++) {
                    int r = mf * 16 + (lane & 15);
                    int c = k16 * 2 + (lane >> 4);
                    ldsm_x4(a[mf][0], a[mf][1], a[mf][2], a[mf][3],
                            sA + r * 128 + ((c ^ (r & 7)) * 16));
                }
                uint32_t bf[4][2];
                #pragma unroll
                for (int nf4 = 0; nf4 < 2; nf4++) {
                    int r = wid * 32 + nf4 * 16 + (lane & 7) + ((lane >> 4) & 1) * 8;
                    int c = k16 * 2 + ((lane >> 3) & 1);
                    uint32_t r0, r1, r2, r3;
                    ldsm_x4(r0, r1, r2, r3, sb + ASM_KV + r * 128 + ((c ^ (r & 7)) * 16));
                    bf[nf4*2][0] = r0; bf[nf4*2][1] = r1;
                    bf[nf4*2+1][0] = r2; bf[nf4*2+1][1] = r3;
                }
                #pragma unroll
                for (int mf = 0; mf < 2; mf++)
                    #pragma unroll
                    for (int nf = 0; nf < 4; nf++)
                        mma16816(acc[mf][nf], a[mf][0], a[mf][1], a[mf][2], a[mf][3],
                                 bf[nf][0], bf[nf][1]);
            }
        }
        const int g = lane >> 2, q = lane & 3;
        #pragma unroll
        for (int mf = 0; mf < 2; mf++)
            #pragma unroll
            for (int nf = 0; nf < 4; nf++) {
                int row = mf * 16 + g;
                int col = half * 256 + wid * 32 + nf * 8 + q * 2;
                S[row*520 + col]       = acc[mf][nf][0];
                S[row*520 + col + 1]   = acc[mf][nf][1];
                S[(row+8)*520 + col]   = acc[mf][nf][2];
                S[(row+8)*520 + col+1] = acc[mf][nf][3];
            }
        __syncthreads();
    }

    for (int idx = tid; idx < 32*9; idx += 256) {
        int t = idx / 9, dd = idx % 9;
        int s = tq0 + t + dd - 4;
        if (s >= 0 && s < NT) S[t*520 + s] += rq[t*12 + dd];
    }
    __syncthreads();
    {
        int r = tid >> 3, l = tid & 7;
        float* row = S + r*520;
        float m = -1e30f;
        for (int j = l; j < NT; j += 8) m = fmaxf(m, row[j]);
        m = fmaxf(m, __shfl_xor_sync(0xffffffffu, m, 1));
        m = fmaxf(m, __shfl_xor_sync(0xffffffffu, m, 2));
        m = fmaxf(m, __shfl_xor_sync(0xffffffffu, m, 4));
        float sum = 0.f;
        for (int j = l; j < NT; j += 8) { float e = fexp(row[j] - m); row[j] = e; sum += e; }
        sum += __shfl_xor_sync(0xffffffffu, sum, 1);
        sum += __shfl_xor_sync(0xffffffffu, sum, 2);
        sum += __shfl_xor_sync(0xffffffffu, sum, 4);
        float inv = 1.f / sum;
        for (int j = l; j < NT; j += 8) row[j] *= inv;
    }
    __syncthreads();

    #pragma unroll
    for (int i = 0; i < 64; i++) {
        int idx = tid + i * 256;
        int s = idx & 511, t = idx >> 9;
        float p = S[t*520 + s];
        int buf = s >> 6, col = s & 63;
        uint32_t off = (uint32_t)buf*4096 + t*128 + ((((uint32_t)col>>3) ^ (t&7))*16) + (col&7)*2;
        *(__nv_bfloat16*)(smraw + ASM_KV + off) = __float2bfloat16_rn(p);
    }
    __syncthreads();

    #pragma unroll
    for (int i = 0; i < 16; i++) {
        int ch = tid + i * 256;
        int c16 = ch & 7, d = (ch >> 3) & 63, buf = ch >> 9;
        CP_ASYNC16(sb + ASM_S + (uint32_t)buf*8192 + (uint32_t)d*128 + (((uint32_t)c16 ^ (d&7))*16),
                   vbp + (size_t)d*NT + buf*64 + c16*8);
    }
    CP_COMMIT(); CP_WAIT0();
    __syncthreads();

    {
        const int kg = wid >> 2;
        const int nw = (wid & 3) * 16;
        float po[2][2][4];
        #pragma unroll
        for (int i = 0; i < 2; i++)
            #pragma unroll
            for (int j = 0; j < 2; j++)
                #pragma unroll
                for (int q = 0; q < 4; q++) po[i][j][q] = 0.f;

        #pragma unroll
        for (int gI = 0; gI < 4; gI++) {
            const uint32_t sA = sb + ASM_KV + (uint32_t)(kg*4 + gI) * 4096;
            const uint32_t sB = sb + ASM_S  + (uint32_t)(kg*4 + gI) * 8192;
            #pragma unroll
            for (int k16 = 0; k16 < 4; k16++) {
                uint32_t a[2][4];
                #pragma unroll
                for (int mf = 0; mf < 2; mf++) {
                    int r = mf * 16 + (lane & 15);
                    int c = k16 * 2 + (lane >> 4);
                    ldsm_x4(a[mf][0], a[mf][1], a[mf][2], a[mf][3],
                            sA + r * 128 + ((c ^ (r & 7)) * 16));
                }
                int r = nw + (lane & 7) + ((lane >> 4) & 1) * 8;
                int c = k16 * 2 + ((lane >> 3) & 1);
                uint32_t r0, r1, r2, r3;
                ldsm_x4(r0, r1, r2, r3, sB + r * 128 + ((c ^ (r & 7)) * 16));
                uint32_t bf[2][2] = {{r0, r1}, {r2, r3}};
                #pragma unroll
                for (int mf = 0; mf < 2; mf++)
                    #pragma unroll
                    for (int nf = 0; nf < 2; nf++)
                        mma16816(po[mf][nf], a[mf][0], a[mf][1], a[mf][2], a[mf][3],
                                 bf[nf][0], bf[nf][1]);
            }
        }

        float* red = (float*)(smraw + ASM_Q);
        const int g = lane >> 2, q = lane & 3;
        if (kg == 1) {
            #pragma unroll
            for (int mf = 0; mf < 2; mf++)
                #pragma unroll
                for (int nf = 0; nf < 2; nf++) {
                    int row = mf * 16 + g;
                    int col = nw + nf * 8 + q * 2;
                    red[row*64 + col]       = po[mf][nf][0];
                    red[row*64 + col + 1]   = po[mf][nf][1];
                    red[(row+8)*64 + col]   = po[mf][nf][2];
                    red[(row+8)*64 + col+1] = po[mf][nf][3];
                }
        }
        __syncthreads();
        if (kg == 0) {
            #pragma unroll
            for (int mf = 0; mf < 2; mf++)
                #pragma unroll
                for (int nf = 0; nf < 2; nf++) {
                    int row = mf * 16 + g;
                    int col = nw + nf * 8 + q * 2;
                    red[row*64 + col]       += po[mf][nf][0];
                    red[row*64 + col + 1]   += po[mf][nf][1];
                    red[(row+8)*64 + col]   += po[mf][nf][2];
                    red[(row+8)*64 + col+1] += po[mf][nf][3];
                }
        }
        __syncthreads();
    }

    {
        float* red = (float*)(smraw + ASM_Q);
        #pragma unroll
        for (int i = 0; i < 8; i++) {
            int idx = tid + i * 256;
            int d = idx & 63, t = idx >> 6;
            float out = red[t*64 + d];
            int tg = tq0 + t;
            #pragma unroll
            for (int dd = 0; dd < 9; dd++) {
                int s = tg + dd - 4;
                if (s >= 0 && s < NT) {
                    int buf = s >> 6, col = s & 63;
                    uint32_t off = (uint32_t)buf*4096 + t*128 + ((((uint32_t)col>>3) ^ (t&7))*16) + (col&7)*2;
                    float p = __bfloat162float(*(__nv_bfloat16*)(smraw + ASM_KV + off));
                    out += p * relv[dd*64 + d];
                }
            }
            __nv_bfloat16 hi, lo; split2(out, hi, lo);
            size_t row = ((size_t)b*NTP + 1 + tg) * (2*NC) + h*NDK;
            bbo[row + d]      = hi;
            bbo[row + NC + d] = lo;
        }
    }
}

// ================= fused residual add + LN (+ bb1 emission | final output) ====
__global__ void __launch_bounds__(256) add_ln_kernel(const float* __restrict__ gam,
                                                     const float* __restrict__ bet,
                                                     __nv_bfloat16* __restrict__ bbo,
                                                     float* __restrict__ finout,
                                                     const float* __restrict__ msk) {
    extern __shared__ float smv[];
    __shared__ float s_sum[16][16], s_sq[16][16];
    __shared__ float s_mean[16], s_rstd[16];
    const int b  = blockIdx.y;
    const int t0 = blockIdx.x * 16;
    const int l  = threadIdx.x & 15;
    const int cg = threadIdx.x >> 4;

    const float* xb = g_x + (size_t)b*NC*NT + t0 + l;
    const float* yb = g_y + (size_t)b*NC*NT + t0 + l;

    float sum = 0.f, sq = 0.f;
    for (int c = cg; c < NC; c += 16) {
        float v = xb[(size_t)c*NT] + yb[(size_t)c*NT];
        smv[c*17 + l] = v;
        sum += v; sq += v*v;
    }
    s_sum[cg][l] = sum; s_sq[cg][l] = sq;
    __syncthreads();
    if (threadIdx.x < 16) {
        float s = 0.f, q = 0.f;
        #pragma unroll
        for (int g = 0; g < 16; g++) { s += s_sum[g][threadIdx.x]; q += s_sq[g][threadIdx.x]; }
        float mean = s * (1.f/NC);
        float var  = q * (1.f/NC) - mean*mean;
        s_mean[threadIdx.x] = mean;
        s_rstd[threadIdx.x] = rsqrtf(var + 1e-5f);
    }
    __syncthreads();

    if (finout) {
        float mk = msk[b*NT + t0 + l];
        float* oo = finout + (size_t)b*NC*NT + t0 + l;
        for (int c = cg; c < NC; c += 16) {
            float nv = (smv[c*17 + l] - s_mean[l]) * s_rstd[l] * gam[c] + bet[c];
            oo[(size_t)c*NT] = nv * mk;
        }
        return;
    }

    float* xo = g_x + (size_t)b*NC*NT + t0 + l;
    for (int c = cg; c < NC; c += 16) {
        float nv = (smv[c*17 + l] - s_mean[l]) * s_rstd[l] * gam[c] + bet[c];
        xo[(size_t)c*NT] = nv;
        smv[c*17 + l] = nv;
    }
    __syncthreads();
    for (int j = threadIdx.x; j < 16*NC; j += 256) {
        int t = j / NC, c = j - (j / NC) * NC;
        __nv_bfloat16 hi, lo; split2(smv[c*17 + t], hi, lo);
        size_t row = ((size_t)b*NTP + 1 + t0 + t) * (2*NC);
        bbo[row + c] = hi;
        bbo[row + NC + c] = lo;
    }
}

// ================= host =================
extern "C" void kernel_launch(void* const* d_in, const int* in_sizes, int n_in,
                              void* d_out, int out_size) {
    const float* x    = (const float*)d_in[0];
    const float* msk  = (const float*)d_in[1];
    const float* Wq   = (const float*)d_in[2];
    const float* bq   = (const float*)d_in[3];
    const float* Wk   = (const float*)d_in[4];
    const float* bk   = (const float*)d_in[5];
    const float* Wv   = (const float*)d_in[6];
    const float* bv   = (const float*)d_in[7];
    const float* Wo   = (const float*)d_in[8];
    const float* bo   = (const float*)d_in[9];
    const float* relk = (const float*)d_in[10];
    const float* relv = (const float*)d_in[11];
    const float* W1   = (const float*)d_in[12];
    const float* b1   = (const float*)d_in[13];
    const float* W2   = (const float*)d_in[14];
    const float* b2   = (const float*)d_in[15];
    const float* g1   = (const float*)d_in[16];
    const float* be1  = (const float*)d_in[17];
    const float* g2   = (const float*)d_in[18];
    const float* be2  = (const float*)d_in[19];
    float* out = (float*)d_out;

    float *px, *py, *pbqkv, *pq;
    __nv_bfloat16 *pwqkv, *pwo, *pw1, *pw2, *pbb1, *pbb2, *pkb, *pvb;
    cudaGetSymbolAddress((void**)&px,    g_x);
    cudaGetSymbolAddress((void**)&pq,    g_q);
    cudaGetSymbolAddress((void**)&py,    g_y);
    cudaGetSymbolAddress((void**)&pwqkv, g_wqkv);
    cudaGetSymbolAddress((void**)&pwo,   g_wo);
    cudaGetSymbolAddress((void**)&pw1,   g_w1);
    cudaGetSymbolAddress((void**)&pw2,   g_w2);
    cudaGetSymbolAddress((void**)&pbqkv, g_bqkv);
    cudaGetSymbolAddress((void**)&pbb1,  g_bb1);
    cudaGetSymbolAddress((void**)&pbb2,  g_bb2);
    cudaGetSymbolAddress((void**)&pkb,   g_kb);
    cudaGetSymbolAddress((void**)&pvb,   g_vb);

    cudaFuncSetAttribute(attn_kernel, cudaFuncAttributeMaxDynamicSharedMemorySize, ASM_TOT);
    const int smem_ln = NC * 17 * 4;
    cudaFuncSetAttribute(add_ln_kernel, cudaFuncAttributeMaxDynamicSharedMemorySize, smem_ln);
    const int smem_gemm = 3 * 32768;
    cudaFuncSetAttribute(mma_gemm<3*NC, NC,  1, false, false, true >, cudaFuncAttributeMaxDynamicSharedMemorySize, smem_gemm);
    cudaFuncSetAttribute(mma_gemm<NFC,  NC,  3, true,  true,  false>, cudaFuncAttributeMaxDynamicSharedMemorySize, smem_gemm);
    const int smem_gemm64 = 3 * 24576;
    cudaFuncSetAttribute(mma_gemm_t64<NC, NC,  1>, cudaFuncAttributeMaxDynamicSharedMemorySize, smem_gemm64);
    cudaFuncSetAttribute(mma_gemm_t64<NC, NFC, 3>, cudaFuncAttributeMaxDynamicSharedMemorySize, smem_gemm64);

    {
        int nq = NL*NC*NC;
        convert_small<<<(nq+255)/256, 256>>>(Wq, Wk, Wv, Wo, pwqkv, pwo, nq);
        int tot = NB*NC*NT + NL*3*NC + NB*2*(2*NC) + NB*2*(2*NFC);
        misc_init<<<(tot+255)/256, 256>>>(x, msk, bq, bk, bv);
        im2col_pad<<<dim3(NC/32, NT/32, NB), 256>>>(px, pbb1, NC);
    }

    const dim3 gqkv (3*NC/128, NT/128, NB);
    const dim3 gproj64(NC/128, NT/64,  NB);
    const dim3 gffn1(NFC/128,  NT/128, NB);
    const dim3 gln(NT/16, NB);

    for (int i = 0; i < NL; i++) {
        mma_gemm<3*NC, NC, 1, false, false, true><<<gqkv, 256, smem_gemm>>>(
            pwqkv + (size_t)i*3*NC*NC*2, pbqkv + i*3*NC, pbb1, pq, pkb, pvb);

        attn_kernel<<<dim3(NT/32, NH, NB), 256, ASM_TOT>>>(relk, relv, pbb1);

        mma_gemm_t64<NC, NC, 1><<<gproj64, 256, smem_gemm64>>>(
            pwo + (size_t)i*NC*NC*2, bo + i*NC, pbb1, py);
        add_ln_kernel<<<gln, 256, smem_ln>>>(g1 + i*NC, be1 + i*NC, pbb1, nullptr, nullptr);

        if (i == 0) {
            int n1 = NL*3*NFC*(NC/8);
            convert_w_tap<<<(n1+255)/256, 256>>>(W1, pw1, NFC, NC, n1);
            int n2 = NL*3*NC*(NFC/8);
            convert_w_tap<<<(n2+255)/256, 256>>>(W2, pw2, NC, NFC, n2);
        }

        mma_gemm<NFC, NC, 3, true, true, false><<<gffn1, 256, smem_gemm>>>(
            pw1 + (size_t)i*3*NFC*NC*2, b1 + i*NFC, pbb1, pbb2, nullptr, nullptr);
        mma_gemm_t64<NC, NFC, 3><<<gproj64, 256, smem_gemm64>>>(
            pw2 + (size_t)i*3*NC*NFC*2, b2 + i*NC, pbb2, py);

        if (i == NL - 1) {
            add_ln_kernel<<<gln, 256, smem_ln>>>(g2 + i*NC, be2 + i*NC, pbb1, out, msk);
        } else {
            add_ln_kernel<<<gln, 256, smem_ln>>>(g2 + i*NC, be2 + i*NC, pbb1, nullptr, nullptr);
        }
    }
}

// round 16
// speedup vs baseline: 1.5300x; 1.5300x over previous
#include <cuda_runtime.h>
#include <cuda_bf16.h>
#include <cstdint>
#include <math.h>

#define NB 8
#define NT 512
#define NC 768
#define NFC 3072
#define NH 12
#define NL 6
#define NDK 64
#define Q_SCALE 0.125f
#define NTP (NT + 2)

// ---------------- scratch ----------------
__device__ float g_x  [NB*NC*NT];
__device__ float g_q  [NB*NC*NT];        // Q only, fp32 [b][C][t]
__device__ float g_y  [NB*NC*NT];
__device__ __nv_bfloat16 g_kb[(size_t)NB*NH*NT*NDK];   // K bf16 [b,h][s][d]
__device__ __nv_bfloat16 g_vb[(size_t)NB*NH*NDK*NT];   // V bf16 [b,h][d][s]

// A weights 3-segment per row: [Wh | Wl | Wh], row len 3*CIN
__device__ __nv_bfloat16 g_wqkv[(size_t)NL*3*NC*NC*3];
__device__ __nv_bfloat16 g_wo  [(size_t)NL*NC*NC*3];
__device__ __nv_bfloat16 g_w1  [(size_t)NL*3*NFC*NC*3];
__device__ __nv_bfloat16 g_w2  [(size_t)NL*3*NC*NFC*3];
__device__ float         g_bqkv[NL*3*NC];
__device__ __nv_bfloat16 g_bb1[(size_t)NB*NTP*NC*2];
__device__ __nv_bfloat16 g_bb2[(size_t)NB*NTP*NFC*2];

__device__ __forceinline__ void split2(float v, __nv_bfloat16& hi, __nv_bfloat16& lo) {
    hi = __float2bfloat16_rn(v);
    lo = __float2bfloat16_rn(v - __bfloat162float(hi));
}

__device__ __forceinline__ float fexp(float x) {
    float y = x * 1.4426950408889634f;
    float n = rintf(y);
    float f = y - n;
    float p = 0.0013333558146428443f;
    p = fmaf(p, f, 0.009618129107628477f);
    p = fmaf(p, f, 0.05550410866482158f);
    p = fmaf(p, f, 0.2402265069591007f);
    p = fmaf(p, f, 0.6931471805599453f);
    p = fmaf(p, f, 1.0f);
    return __int_as_float(__float_as_int(p) + (((int)n) << 23));
}

// ================= conversions =================
__global__ void convert_small(const float* __restrict__ Wq, const float* __restrict__ Wk,
                              const float* __restrict__ Wv, const float* __restrict__ Wo,
                              __nv_bfloat16* __restrict__ oq, __nv_bfloat16* __restrict__ oo, int n) {
    int idx = blockIdx.x * 256 + threadIdx.x;
    if (idx >= n) return;
    int c = idx % NC;
    int m = (idx / NC) % NC;
    int l = idx / (NC * NC);
    const int KPA = 3 * NC;
    float vals[3] = { Wq[idx] * Q_SCALE, Wk[idx], Wv[idx] };
    size_t lb = (size_t)l * (3*NC) * KPA;
    #pragma unroll
    for (int s = 0; s < 3; s++) {
        __nv_bfloat16 hi, lo; split2(vals[s], hi, lo);
        size_t base = lb + (size_t)(s * NC + m) * KPA;
        oq[base + c] = hi; oq[base + NC + c] = lo; oq[base + 2*NC + c] = hi;
    }
    __nv_bfloat16 hi, lo; split2(Wo[idx], hi, lo);
    size_t base = ((size_t)l * NC + m) * KPA;
    oo[base + c] = hi; oo[base + NC + c] = lo; oo[base + 2*NC + c] = hi;
}

__global__ void convert_w_tap(const float* __restrict__ w, __nv_bfloat16* __restrict__ o,
                              int M, int CIN, int n8) {
    int idx = blockIdx.x * 256 + threadIdx.x;
    if (idx >= n8) return;                     // n8 = NL*3*M*(CIN/8)
    int k  = idx % 3;
    int c8 = (idx / 3) % (CIN / 8);
    int m  = (idx / 3 / (CIN / 8)) % M;
    int l  = idx / 3 / (CIN / 8) / M;
    const float* src = w + (((size_t)((size_t)l * M + m) * CIN + c8 * 8) * 3 + k);
    __nv_bfloat16 hb[8], lb[8];
    #pragma unroll
    for (int j = 0; j < 8; j++) split2(src[j * 3], hb[j], lb[j]);
    size_t p = ((size_t)(l * 3 + k) * M + m) * (size_t)(3 * CIN) + c8 * 8;
    *(uint4*)(o + p)           = *(uint4*)hb;
    *(uint4*)(o + p + CIN)     = *(uint4*)lb;
    *(uint4*)(o + p + 2*CIN)   = *(uint4*)hb;
}

__global__ void misc_init(const float* __restrict__ x, const float* __restrict__ msk,
                          const float* __restrict__ bq, const float* __restrict__ bk,
                          const float* __restrict__ bv) {
    int idx = blockIdx.x * 256 + threadIdx.x;
    const int N0 = NB*NC*NT;
    if (idx < N0) {
        int t = idx % NT, b = idx / (NC*NT);
        g_x[idx] = x[idx] * msk[b*NT + t];
        return;
    }
    idx -= N0;
    const int N1 = NL*3*NC;
    if (idx < N1) {
        int j = idx % (3*NC), l = idx / (3*NC);
        g_bqkv[idx] = (j < NC) ? bq[l*NC + j] * Q_SCALE
                    : (j < 2*NC) ? bk[l*NC + j - NC] : bv[l*NC + j - 2*NC];
        return;
    }
    idx -= N1;
    const int N2 = NB*2*(2*NC);
    if (idx < N2) {
        int b = idx / (2*2*NC), r = (idx / (2*NC)) & 1, c = idx % (2*NC);
        g_bb1[((size_t)b*NTP + (r ? NT+1 : 0)) * (2*NC) + c] = __float2bfloat16(0.f);
        return;
    }
    idx -= N2;
    const int N3 = NB*2*(2*NFC);
    if (idx < N3) {
        int b = idx / (2*2*NFC), r = (idx / (2*NFC)) & 1, c = idx % (2*NFC);
        g_bb2[((size_t)b*NTP + (r ? NT+1 : 0)) * (2*NFC) + c] = __float2bfloat16(0.f);
    }
}

__global__ void __launch_bounds__(256) im2col_pad(const float* __restrict__ act,
                                                  __nv_bfloat16* __restrict__ bp, int CIN) {
    __shared__ float tile[32][33];
    const int c0 = blockIdx.x * 32, t00 = blockIdx.y * 32, b = blockIdx.z;
    #pragma unroll
    for (int i = 0; i < 4; i++) {
        int idx = threadIdx.x + i * 256;
        int cl = idx >> 5, tl = idx & 31;
        tile[cl][tl] = act[((size_t)b * CIN + c0 + cl) * NT + t00 + tl];
    }
    __syncthreads();
    #pragma unroll
    for (int i = 0; i < 4; i++) {
        int idx = threadIdx.x + i * 256;
        int tl = idx >> 5, cl = idx & 31;
        __nv_bfloat16 hi, lo; split2(tile[cl][tl], hi, lo);
        size_t row = ((size_t)b * NTP + 1 + t00 + tl) * (2*CIN);
        bp[row + c0 + cl] = hi;
        bp[row + CIN + c0 + cl] = lo;
    }
}

// ================= mma.sync primitives =================
__device__ __forceinline__ uint32_t smem_u32(const void* p) {
    uint32_t a;
    asm("{ .reg .u64 t; cvta.to.shared.u64 t, %1; cvt.u32.u64 %0, t; }" : "=r"(a) : "l"(p));
    return a;
}
#define CP_ASYNC16(dst, src) asm volatile("cp.async.cg.shared.global [%0], [%1], 16;" :: "r"(dst), "l"(src))
#define CP_COMMIT()          asm volatile("cp.async.commit_group;" ::: "memory")
#define CP_WAIT1()           asm volatile("cp.async.wait_group 1;" ::: "memory")
#define CP_WAIT0()           asm volatile("cp.async.wait_group 0;" ::: "memory")

__device__ __forceinline__ void ldsm_x4(uint32_t& r0, uint32_t& r1, uint32_t& r2, uint32_t& r3, uint32_t a) {
    asm volatile("ldmatrix.sync.aligned.m8n8.x4.shared.b16 {%0,%1,%2,%3}, [%4];"
        : "=r"(r0), "=r"(r1), "=r"(r2), "=r"(r3) : "r"(a));
}
__device__ __forceinline__ void mma16816(float* d, uint32_t a0, uint32_t a1, uint32_t a2, uint32_t a3,
                                         uint32_t b0, uint32_t b1) {
    asm volatile("mma.sync.aligned.m16n8k16.row.col.f32.bf16.bf16.f32 "
        "{%0,%1,%2,%3}, {%4,%5,%6,%7}, {%8,%9}, {%0,%1,%2,%3};"
        : "+f"(d[0]), "+f"(d[1]), "+f"(d[2]), "+f"(d[3])
        : "r"(a0), "r"(a1), "r"(a2), "r"(a3), "r"(b0), "r"(b1));
}

// ---------------- 128m x 128t tile (QKV, FFN1) ----------------
template<int MTOT, int CIN, int TAPS, bool RELU, bool BB2, bool QKV>
__global__ void __launch_bounds__(256, 2) mma_gemm(
    const __nv_bfloat16* __restrict__ Aw, const float* __restrict__ bias,
    const __nv_bfloat16* __restrict__ Bb, void* __restrict__ outp,
    __nv_bfloat16* __restrict__ kb, __nv_bfloat16* __restrict__ vb)
{
    constexpr int KPA = CIN * 3;
    constexpr int KPB = CIN * 2;
    constexpr int NKC = KPA / 64;
    constexpr int TOT = NKC * TAPS;
    constexpr int OFF0 = (TAPS == 1) ? 1 : 0;

    extern __shared__ __align__(1024) char smem[];
    const uint32_t sbase = smem_u32(smem);
    const int tid = threadIdx.x;
    const int wid = tid >> 5, lane = tid & 31;
    const int m0 = blockIdx.x * 128;
    const int t0 = blockIdx.y * 128;
    const int b  = blockIdx.z;

    const __nv_bfloat16* Ag = Aw + (size_t)m0 * KPA;
    const __nv_bfloat16* Bg = Bb + ((size_t)b * NTP + t0 + OFF0) * KPB;

    const int wm = (wid >> 1) * 32;
    const int wn = (wid & 1) * 64;

    float acc[2][8][4];
    #pragma unroll
    for (int i = 0; i < 2; i++)
        #pragma unroll
        for (int j = 0; j < 8; j++)
            #pragma unroll
            for (int q = 0; q < 4; q++) acc[i][j][q] = 0.f;

    auto stage_off = [&](int st) { return sbase + st * 32768u; };

    #define LOAD_STAGE(ST, IC) do { \
        const int _tap = (TAPS == 1) ? 0 : ((IC) / NKC); \
        const int _kc  = ((IC) - _tap * NKC) * 64; \
        const int _bk  = (_kc >= CIN) ? _kc - CIN : _kc; \
        uint32_t sa = stage_off(ST); \
        const __nv_bfloat16* _Asrc = Ag + (size_t)_tap * MTOT * KPA + _kc; \
        const __nv_bfloat16* _Bsrc = Bg + (size_t)_tap * KPB + _bk; \
        _Pragma("unroll") \
        for (int it = 0; it < 8; it++) { \
            int idx = tid + it * 256; \
            if (idx < 1024) { \
                int r = idx >> 3, c = idx & 7; \
                CP_ASYNC16(sa + r * 128 + ((c ^ (r & 7)) * 16), _Asrc + (size_t)r * KPA + c * 8); \
            } else { \
                int j2 = idx - 1024; int r = j2 >> 3, c = j2 & 7; \
                CP_ASYNC16(sa + 16384 + r * 128 + ((c ^ (r & 7)) * 16), _Bsrc + (size_t)r * KPB + c * 8); \
            } \
        } \
    } while (0)

    LOAD_STAGE(0, 0);
    CP_COMMIT();
    LOAD_STAGE(1, 1);
    CP_COMMIT();

    for (int ic = 0; ic < TOT; ic++) {
        CP_WAIT1();
        __syncthreads();
        if (ic + 2 < TOT) {
            int st = (ic + 2) % 3;
            LOAD_STAGE(st, ic + 2);
            CP_COMMIT();
        }

        const uint32_t sA = stage_off(ic % 3);
        const uint32_t sB = sA + 16384;

        #pragma unroll
        for (int k16 = 0; k16 < 4; k16++) {
            uint32_t a[2][4];
            #pragma unroll
            for (int mf = 0; mf < 2; mf++) {
                int r = wm + mf * 16 + (lane & 15);
                int c = k16 * 2 + (lane >> 4);
                ldsm_x4(a[mf][0], a[mf][1], a[mf][2], a[mf][3],
                        sA + r * 128 + ((c ^ (r & 7)) * 16));
            }
            uint32_t bf[8][2];
            #pragma unroll
            for (int nf4 = 0; nf4 < 4; nf4++) {
                int r = wn + nf4 * 16 + (lane & 7) + ((lane >> 4) & 1) * 8;
                int c = k16 * 2 + ((lane >> 3) & 1);
                uint32_t r0, r1, r2, r3;
                ldsm_x4(r0, r1, r2, r3, sB + r * 128 + ((c ^ (r & 7)) * 16));
                bf[nf4*2][0] = r0; bf[nf4*2][1] = r1;
                bf[nf4*2+1][0] = r2; bf[nf4*2+1][1] = r3;
            }
            #pragma unroll
            for (int mf = 0; mf < 2; mf++)
                #pragma unroll
                for (int nf = 0; nf < 8; nf++)
                    mma16816(acc[mf][nf], a[mf][0], a[mf][1], a[mf][2], a[mf][3],
                             bf[nf][0], bf[nf][1]);
        }
    }
    #undef LOAD_STAGE

    const int gr = lane >> 2, qc = lane & 3;
    #pragma unroll
    for (int mf = 0; mf < 2; mf++) {
        int mA = m0 + wm + mf * 16 + gr;
        int mB = mA + 8;
        float bsA = bias[mA], bsB = bias[mB];
        #pragma unroll
        for (int nf = 0; nf < 8; nf++) {
            int tc = wn + nf * 8 + qc * 2;
            float v0 = acc[mf][nf][0] + bsA, v1 = acc[mf][nf][1] + bsA;
            float v2 = acc[mf][nf][2] + bsB, v3 = acc[mf][nf][3] + bsB;
            if (RELU) { v0 = fmaxf(v0,0.f); v1 = fmaxf(v1,0.f); v2 = fmaxf(v2,0.f); v3 = fmaxf(v3,0.f); }
            if (BB2) {
                __nv_bfloat16* bb = (__nv_bfloat16*)outp;
                size_t r0w = ((size_t)b*NTP + 1 + t0 + tc) * (2*MTOT);
                size_t r1w = r0w + (2*MTOT);
                __nv_bfloat16 h, l;
                split2(v0, h, l); bb[r0w + mA] = h; bb[r0w + MTOT + mA] = l;
                split2(v1, h, l); bb[r1w + mA] = h; bb[r1w + MTOT + mA] = l;
                split2(v2, h, l); bb[r0w + mB] = h; bb[r0w + MTOT + mB] = l;
                split2(v3, h, l); bb[r1w + mB] = h; bb[r1w + MTOT + mB] = l;
            } else if (QKV && m0 >= NC) {
                const bool isK = (m0 < 2*NC);
                int moff = mA - (isK ? NC : 2*NC);
                int hh = moff >> 6, dA = moff & 63;
                int st = t0 + tc;
                if (isK) {
                    __nv_bfloat16* kp = kb + ((size_t)b*NH + hh) * NT * NDK;
                    kp[(size_t)st*NDK + dA]         = __float2bfloat16_rn(v0);
                    kp[(size_t)(st+1)*NDK + dA]     = __float2bfloat16_rn(v1);
                    kp[(size_t)st*NDK + dA + 8]     = __float2bfloat16_rn(v2);
                    kp[(size_t)(st+1)*NDK + dA + 8] = __float2bfloat16_rn(v3);
                } else {
                    __nv_bfloat16* vp = vb + ((size_t)b*NH + hh) * NDK * NT;
                    *(__nv_bfloat162*)(vp + (size_t)dA*NT + st)     = __nv_bfloat162{__float2bfloat16_rn(v0), __float2bfloat16_rn(v1)};
                    *(__nv_bfloat162*)(vp + (size_t)(dA+8)*NT + st) = __nv_bfloat162{__float2bfloat16_rn(v2), __float2bfloat16_rn(v3)};
                }
            } else {
                const int MST = QKV ? NC : MTOT;
                float* out = (float*)outp;
                float* rowA = out + ((size_t)b * MST + mA) * NT + t0;
                float* rowB = out + ((size_t)b * MST + mB) * NT + t0;
                *(float2*)(rowA + tc) = make_float2(v0, v1);
                *(float2*)(rowB + tc) = make_float2(v2, v3);
            }
        }
    }
}

// ---------------- 128m x 64t tile, 3 CTAs/SM (O-proj, FFN2) ----------------
template<int MTOT, int CIN, int TAPS>
__global__ void __launch_bounds__(256, 3) mma_gemm_t64(
    const __nv_bfloat16* __restrict__ Aw, const float* __restrict__ bias,
    const __nv_bfloat16* __restrict__ Bb, float* __restrict__ out)
{
    constexpr int KPA = CIN * 3;
    constexpr int KPB = CIN * 2;
    constexpr int NKC = KPA / 64;
    constexpr int TOT = NKC * TAPS;
    constexpr int OFF0 = (TAPS == 1) ? 1 : 0;

    extern __shared__ __align__(1024) char smem[];
    const uint32_t sbase = smem_u32(smem);
    const int tid = threadIdx.x;
    const int wid = tid >> 5, lane = tid & 31;
    const int m0 = blockIdx.x * 128;
    const int t0 = blockIdx.y * 64;
    const int b  = blockIdx.z;

    const __nv_bfloat16* Ag = Aw + (size_t)m0 * KPA;
    const __nv_bfloat16* Bg = Bb + ((size_t)b * NTP + t0 + OFF0) * KPB;

    const int wm = (wid >> 1) * 32;
    const int wn = (wid & 1) * 32;

    float acc[2][4][4];
    #pragma unroll
    for (int i = 0; i < 2; i++)
        #pragma unroll
        for (int j = 0; j < 4; j++)
            #pragma unroll
            for (int q = 0; q < 4; q++) acc[i][j][q] = 0.f;

    auto stage_off = [&](int st) { return sbase + st * 24576u; };

    #define LOAD_STAGE64(ST, IC) do { \
        const int _tap = (TAPS == 1) ? 0 : ((IC) / NKC); \
        const int _kc  = ((IC) - _tap * NKC) * 64; \
        const int _bk  = (_kc >= CIN) ? _kc - CIN : _kc; \
        uint32_t sa = stage_off(ST); \
        const __nv_bfloat16* _Asrc = Ag + (size_t)_tap * MTOT * KPA + _kc; \
        const __nv_bfloat16* _Bsrc = Bg + (size_t)_tap * KPB + _bk; \
        _Pragma("unroll") \
        for (int it = 0; it < 6; it++) { \
            int idx = tid + it * 256; \
            if (idx < 1024) { \
                int r = idx >> 3, c = idx & 7; \
                CP_ASYNC16(sa + r * 128 + ((c ^ (r & 7)) * 16), _Asrc + (size_t)r * KPA + c * 8); \
            } else { \
                int j2 = idx - 1024; int r = j2 >> 3, c = j2 & 7; \
                CP_ASYNC16(sa + 16384 + r * 128 + ((c ^ (r & 7)) * 16), _Bsrc + (size_t)r * KPB + c * 8); \
            } \
        } \
    } while (0)

    LOAD_STAGE64(0, 0);
    CP_COMMIT();
    LOAD_STAGE64(1, 1);
    CP_COMMIT();

    for (int ic = 0; ic < TOT; ic++) {
        CP_WAIT1();
        __syncthreads();
        if (ic + 2 < TOT) {
            int st = (ic + 2) % 3;
            LOAD_STAGE64(st, ic + 2);
            CP_COMMIT();
        }

        const uint32_t sA = stage_off(ic % 3);
        const uint32_t sB = sA + 16384;

        #pragma unroll
        for (int k16 = 0; k16 < 4; k16++) {
            uint32_t a[2][4];
            #pragma unroll
            for (int mf = 0; mf < 2; mf++) {
                int r = wm + mf * 16 + (lane & 15);
                int c = k16 * 2 + (lane >> 4);
                ldsm_x4(a[mf][0], a[mf][1], a[mf][2], a[mf][3],
                        sA + r * 128 + ((c ^ (r & 7)) * 16));
            }
            uint32_t bf[4][2];
            #pragma unroll
            for (int nf4 = 0; nf4 < 2; nf4++) {
                int r = wn + nf4 * 16 + (lane & 7) + ((lane >> 4) & 1) * 8;
                int c = k16 * 2 + ((lane >> 3) & 1);
                uint32_t r0, r1, r2, r3;
                ldsm_x4(r0, r1, r2, r3, sB + r * 128 + ((c ^ (r & 7)) * 16));
                bf[nf4*2][0] = r0; bf[nf4*2][1] = r1;
                bf[nf4*2+1][0] = r2; bf[nf4*2+1][1] = r3;
            }
            #pragma unroll
            for (int mf = 0; mf < 2; mf++)
                #pragma unroll
                for (int nf = 0; nf < 4; nf++)
                    mma16816(acc[mf][nf], a[mf][0], a[mf][1], a[mf][2], a[mf][3],
                             bf[nf][0], bf[nf][1]);
        }
    }
    #undef LOAD_STAGE64

    const int gr = lane >> 2, qc = lane & 3;
    #pragma unroll
    for (int mf = 0; mf < 2; mf++) {
        int mA = m0 + wm + mf * 16 + gr;
        int mB = mA + 8;
        float bsA = bias[mA], bsB = bias[mB];
        float* rowA = out + ((size_t)b * MTOT + mA) * NT + t0;
        float* rowB = out + ((size_t)b * MTOT + mB) * NT + t0;
        #pragma unroll
        for (int nf = 0; nf < 4; nf++) {
            int tc = wn + nf * 8 + qc * 2;
            *(float2*)(rowA + tc) = make_float2(acc[mf][nf][0] + bsA, acc[mf][nf][1] + bsA);
            *(float2*)(rowB + tc) = make_float2(acc[mf][nf][2] + bsB, acc[mf][nf][3] + bsB);
        }
    }
}

// ================= tensor-core attention (2 CTAs/SM, cp.async K/V) =================
#define ASM_S   0u
#define ASM_KV  66560u
#define ASM_Q   99328u
#define ASM_RQ  107520u
#define ASM_TOT (107520 + 32*12*4)

__global__ void __launch_bounds__(256, 2) attn_kernel(const float* __restrict__ relk,
                                                      const float* __restrict__ relv,
                                                      __nv_bfloat16* __restrict__ bbo) {
    extern __shared__ __align__(1024) char smraw[];
    const uint32_t sb = smem_u32(smraw);
    float* S  = (float*)(smraw + ASM_S);
    float* rq = (float*)(smraw + ASM_RQ);

    const int tid = threadIdx.x;
    const int wid = tid >> 5, lane = tid & 31;
    const int b = blockIdx.z, h = blockIdx.y;
    const int tq0 = blockIdx.x * 32;
    const float* qg = g_q + ((size_t)b*NC + h*NDK) * NT;
    const __nv_bfloat16* kbp = g_kb + ((size_t)b*NH + h) * NT * NDK;
    const __nv_bfloat16* vbp = g_vb + ((size_t)b*NH + h) * NDK * NT;

    #pragma unroll
    for (int i = 0; i < 8; i++) {
        int idx = tid + i * 256;
        int t = idx & 31, d = idx >> 5;
        float v = qg[(size_t)d*NT + tq0 + t];
        __nv_bfloat16 hi, lo; split2(v, hi, lo);
        uint32_t off = (uint32_t)t*128 + ((((uint32_t)d>>3) ^ (t&7))*16) + (d&7)*2;
        *(__nv_bfloat16*)(smraw + ASM_Q + off)        = hi;
        *(__nv_bfloat16*)(smraw + ASM_Q + 4096 + off) = lo;
    }
    for (int idx = tid; idx < 32*9; idx += 256) {
        int t = idx / 9, dd = idx % 9;
        float s = 0.f;
        #pragma unroll
        for (int d = 0; d < 64; d++) s += qg[(size_t)d*NT + tq0 + t] * relk[dd*64 + d];
        rq[t*12 + dd] = s;
    }
    __syncthreads();

    #pragma unroll
    for (int half = 0; half < 2; half++) {
        #pragma unroll
        for (int i = 0; i < 8; i++) {
            int ch = tid + i * 256;
            int s = ch >> 3, c16 = ch & 7;
            CP_ASYNC16(sb + ASM_KV + (uint32_t)s*128 + (((uint32_t)c16 ^ (s&7))*16),
                       kbp + ((size_t)(half*256 + s))*NDK + c16*8);
        }
        CP_COMMIT(); CP_WAIT0();
        __syncthreads();

        float acc[2][4][4];
        #pragma unroll
        for (int i = 0; i < 2; i++)
            #pragma unroll
            for (int j = 0; j < 4; j++)
                #pragma unroll
                for (int q = 0; q < 4; q++) acc[i][j][q] = 0.f;

        #pragma unroll
        for (int pass = 0; pass < 2; pass++) {
            const uint32_t sA = sb + ASM_Q + pass * 4096;
            #pragma unroll
            for (int k16 = 0; k16 < 4; k16++) {
                uint32_t a[2][4];
                #pragma unroll
                for (int mf = 0; mf < 2; mf++) {
                    int r = mf * 16 + (lane & 15);
                    int c = k16 * 2 + (lane >> 4);
                    ldsm_x4(a[mf][0], a[mf][1], a[mf][2], a[mf][3],
                            sA + r * 128 + ((c ^ (r & 7)) * 16));
                }
                uint32_t bf[4][2];
                #pragma unroll
                for (int nf4 = 0; nf4 < 2; nf4++) {
                    int r = wid * 32 + nf4 * 16 + (lane & 7) + ((lane >> 4) & 1) * 8;
                    int c = k16 * 2 + ((lane >> 3) & 1);
                    uint32_t r0, r1, r2, r3;
                    ldsm_x4(r0, r1, r2, r3, sb + ASM_KV + r * 128 + ((c ^ (r & 7)) * 16));
                    bf[nf4*2][0] = r0; bf[nf4*2][1] = r1;
                    bf[nf4*2+1][0] = r2; bf[nf4*2+1][1] = r3;
                }
                #pragma unroll
                for (int mf = 0; mf < 2; mf++)
                    #pragma unroll
                    for (int nf = 0; nf < 4; nf++)
                        mma16816(acc[mf][nf], a[mf][0], a[mf][1], a[mf][2], a[mf][3],
                                 bf[nf][0], bf[nf][1]);
            }
        }
        const int g = lane >> 2, q = lane & 3;
        #pragma unroll
        for (int mf = 0; mf < 2; mf++)
            #pragma unroll
            for (int nf = 0; nf < 4; nf++) {
                int row = mf * 16 + g;
                int col = half * 256 + wid * 32 + nf * 8 + q * 2;
                S[row*520 + col]       = acc[mf][nf][0];
                S[row*520 + col + 1]   = acc[mf][nf][1];
                S[(row+8)*520 + col]   = acc[mf][nf][2];
                S[(row+8)*520 + col+1] = acc[mf][nf][3];
            }
        __syncthreads();
    }

    for (int idx = tid; idx < 32*9; idx += 256) {
        int t = idx / 9, dd = idx % 9;
        int s = tq0 + t + dd - 4;
        if (s >= 0 && s < NT) S[t*520 + s] += rq[t*12 + dd];
    }
    __syncthreads();
    {
        int r = tid >> 3, l = tid & 7;
        float* row = S + r*520;
        float m = -1e30f;
        for (int j = l; j < NT; j += 8) m = fmaxf(m, row[j]);
        m = fmaxf(m, __shfl_xor_sync(0xffffffffu, m, 1));
        m = fmaxf(m, __shfl_xor_sync(0xffffffffu, m, 2));
        m = fmaxf(m, __shfl_xor_sync(0xffffffffu, m, 4));
        float sum = 0.f;
        for (int j = l; j < NT; j += 8) { float e = fexp(row[j] - m); row[j] = e; sum += e; }
        sum += __shfl_xor_sync(0xffffffffu, sum, 1);
        sum += __shfl_xor_sync(0xffffffffu, sum, 2);
        sum += __shfl_xor_sync(0xffffffffu, sum, 4);
        float inv = 1.f / sum;
        for (int j = l; j < NT; j += 8) row[j] *= inv;
    }
    __syncthreads();

    #pragma unroll
    for (int i = 0; i < 64; i++) {
        int idx = tid + i * 256;
        int s = idx & 511, t = idx >> 9;
        float p = S[t*520 + s];
        int buf = s >> 6, col = s & 63;
        uint32_t off = (uint32_t)buf*4096 + t*128 + ((((uint32_t)col>>3) ^ (t&7))*16) + (col&7)*2;
        *(__nv_bfloat16*)(smraw + ASM_KV + off) = __float2bfloat16_rn(p);
    }
    __syncthreads();

    #pragma unroll
    for (int i = 0; i < 16; i++) {
        int ch = tid + i * 256;
        int c16 = ch & 7, d = (ch >> 3) & 63, buf = ch >> 9;
        CP_ASYNC16(sb + ASM_S + (uint32_t)buf*8192 + (uint32_t)d*128 + (((uint32_t)c16 ^ (d&7))*16),
                   vbp + (size_t)d*NT + buf*64 + c16*8);
    }
    CP_COMMIT(); CP_WAIT0();
    __syncthreads();

    {
        const int kg = wid >> 2;
        const int nw = (wid & 3) * 16;
        float po[2][2][4];
        #pragma unroll
        for (int i = 0; i < 2; i++)
            #pragma unroll
            for (int j = 0; j < 2; j++)
                #pragma unroll
                for (int q = 0; q < 4; q++) po[i][j][q] = 0.f;

        #pragma unroll
        for (int gI = 0; gI < 4; gI++) {
            const uint32_t sA = sb + ASM_KV + (uint32_t)(kg*4 + gI) * 4096;
            const uint32_t sB = sb + ASM_S  + (uint32_t)(kg*4 + gI) * 8192;
            #pragma unroll
            for (int k16 = 0; k16 < 4; k16++) {
                uint32_t a[2][4];
                #pragma unroll
                for (int mf = 0; mf < 2; mf++) {
                    int r = mf * 16 + (lane & 15);
                    int c = k16 * 2 + (lane >> 4);
                    ldsm_x4(a[mf][0], a[mf][1], a[mf][2], a[mf][3],
                            sA + r * 128 + ((c ^ (r & 7)) * 16));
                }
                int r = nw + (lane & 7) + ((lane >> 4) & 1) * 8;
                int c = k16 * 2 + ((lane >> 3) & 1);
                uint32_t r0, r1, r2, r3;
                ldsm_x4(r0, r1, r2, r3, sB + r * 128 + ((c ^ (r & 7)) * 16));
                uint32_t bf[2][2] = {{r0, r1}, {r2, r3}};
                #pragma unroll
                for (int mf = 0; mf < 2; mf++)
                    #pragma unroll
                    for (int nf = 0; nf < 2; nf++)
                        mma16816(po[mf][nf], a[mf][0], a[mf][1], a[mf][2], a[mf][3],
                                 bf[nf][0], bf[nf][1]);
            }
        }

        float* red = (float*)(smraw + ASM_Q);
        const int g = lane >> 2, q = lane & 3;
        if (kg == 1) {
            #pragma unroll
            for (int mf = 0; mf < 2; mf++)
                #pragma unroll
                for (int nf = 0; nf < 2; nf++) {
                    int row = mf * 16 + g;
                    int col = nw + nf * 8 + q * 2;
                    red[row*64 + col]       = po[mf][nf][0];
                    red[row*64 + col + 1]   = po[mf][nf][1];
                    red[(row+8)*64 + col]   = po[mf][nf][2];
                    red[(row+8)*64 + col+1] = po[mf][nf][3];
                }
        }
        __syncthreads();
        if (kg == 0) {
            #pragma unroll
            for (int mf = 0; mf < 2; mf++)
                #pragma unroll
                for (int nf = 0; nf < 2; nf++) {
                    int row = mf * 16 + g;
                    int col = nw + nf * 8 + q * 2;
                    red[row*64 + col]       += po[mf][nf][0];
                    red[row*64 + col + 1]   += po[mf][nf][1];
                    red[(row+8)*64 + col]   += po[mf][nf][2];
                    red[(row+8)*64 + col+1] += po[mf][nf][3];
                }
        }
        __syncthreads();
    }

    {
        float* red = (float*)(smraw + ASM_Q);
        #pragma unroll
        for (int i = 0; i < 8; i++) {
            int idx = tid + i * 256;
            int d = idx & 63, t = idx >> 6;
            float out = red[t*64 + d];
            int tg = tq0 + t;
            #pragma unroll
            for (int dd = 0; dd < 9; dd++) {
                int s = tg + dd - 4;
                if (s >= 0 && s < NT) {
                    int buf = s >> 6, col = s & 63;
                    uint32_t off = (uint32_t)buf*4096 + t*128 + ((((uint32_t)col>>3) ^ (t&7))*16) + (col&7)*2;
                    float p = __bfloat162float(*(__nv_bfloat16*)(smraw + ASM_KV + off));
                    out += p * relv[dd*64 + d];
                }
            }
            __nv_bfloat16 hi, lo; split2(out, hi, lo);
            size_t row = ((size_t)b*NTP + 1 + tg) * (2*NC) + h*NDK;
            bbo[row + d]      = hi;
            bbo[row + NC + d] = lo;
        }
    }
}

// ================= fused residual add + LN (+ bb1 emission | final output) ====
__global__ void __launch_bounds__(256) add_ln_kernel(const float* __restrict__ gam,
                                                     const float* __restrict__ bet,
                                                     __nv_bfloat16* __restrict__ bbo,
                                                     float* __restrict__ finout,
                                                     const float* __restrict__ msk) {
    extern __shared__ float smv[];
    __shared__ float s_sum[16][16], s_sq[16][16];
    __shared__ float s_mean[16], s_rstd[16];
    const int b  = blockIdx.y;
    const int t0 = blockIdx.x * 16;
    const int l  = threadIdx.x & 15;
    const int cg = threadIdx.x >> 4;

    const float* xb = g_x + (size_t)b*NC*NT + t0 + l;
    const float* yb = g_y + (size_t)b*NC*NT + t0 + l;

    float sum = 0.f, sq = 0.f;
    for (int c = cg; c < NC; c += 16) {
        float v = xb[(size_t)c*NT] + yb[(size_t)c*NT];
        smv[c*17 + l] = v;
        sum += v; sq += v*v;
    }
    s_sum[cg][l] = sum; s_sq[cg][l] = sq;
    __syncthreads();
    if (threadIdx.x < 16) {
        float s = 0.f, q = 0.f;
        #pragma unroll
        for (int g = 0; g < 16; g++) { s += s_sum[g][threadIdx.x]; q += s_sq[g][threadIdx.x]; }
        float mean = s * (1.f/NC);
        float var  = q * (1.f/NC) - mean*mean;
        s_mean[threadIdx.x] = mean;
        s_rstd[threadIdx.x] = rsqrtf(var + 1e-5f);
    }
    __syncthreads();

    if (finout) {
        float mk = msk[b*NT + t0 + l];
        float* oo = finout + (size_t)b*NC*NT + t0 + l;
        for (int c = cg; c < NC; c += 16) {
            float nv = (smv[c*17 + l] - s_mean[l]) * s_rstd[l] * gam[c] + bet[c];
            oo[(size_t)c*NT] = nv * mk;
        }
        return;
    }

    float* xo = g_x + (size_t)b*NC*NT + t0 + l;
    for (int c = cg; c < NC; c += 16) {
        float nv = (smv[c*17 + l] - s_mean[l]) * s_rstd[l] * gam[c] + bet[c];
        xo[(size_t)c*NT] = nv;
        smv[c*17 + l] = nv;
    }
    __syncthreads();
    for (int j = threadIdx.x; j < 16*NC; j += 256) {
        int t = j / NC, c = j - (j / NC) * NC;
        __nv_bfloat16 hi, lo; split2(smv[c*17 + t], hi, lo);
        size_t row = ((size_t)b*NTP + 1 + t0 + t) * (2*NC);
        bbo[row + c] = hi;
        bbo[row + NC + c] = lo;
    }
}

// ================= host =================
extern "C" void kernel_launch(void* const* d_in, const int* in_sizes, int n_in,
                              void* d_out, int out_size) {
    const float* x    = (const float*)d_in[0];
    const float* msk  = (const float*)d_in[1];
    const float* Wq   = (const float*)d_in[2];
    const float* bq   = (const float*)d_in[3];
    const float* Wk   = (const float*)d_in[4];
    const float* bk   = (const float*)d_in[5];
    const float* Wv   = (const float*)d_in[6];
    const float* bv   = (const float*)d_in[7];
    const float* Wo   = (const float*)d_in[8];
    const float* bo   = (const float*)d_in[9];
    const float* relk = (const float*)d_in[10];
    const float* relv = (const float*)d_in[11];
    const float* W1   = (const float*)d_in[12];
    const float* b1   = (const float*)d_in[13];
    const float* W2   = (const float*)d_in[14];
    const float* b2   = (const float*)d_in[15];
    const float* g1   = (const float*)d_in[16];
    const float* be1  = (const float*)d_in[17];
    const float* g2   = (const float*)d_in[18];
    const float* be2  = (const float*)d_in[19];
    float* out = (float*)d_out;

    float *px, *py, *pbqkv, *pq;
    __nv_bfloat16 *pwqkv, *pwo, *pw1, *pw2, *pbb1, *pbb2, *pkb, *pvb;
    cudaGetSymbolAddress((void**)&px,    g_x);
    cudaGetSymbolAddress((void**)&pq,    g_q);
    cudaGetSymbolAddress((void**)&py,    g_y);
    cudaGetSymbolAddress((void**)&pwqkv, g_wqkv);
    cudaGetSymbolAddress((void**)&pwo,   g_wo);
    cudaGetSymbolAddress((void**)&pw1,   g_w1);
    cudaGetSymbolAddress((void**)&pw2,   g_w2);
    cudaGetSymbolAddress((void**)&pbqkv, g_bqkv);
    cudaGetSymbolAddress((void**)&pbb1,  g_bb1);
    cudaGetSymbolAddress((void**)&pbb2,  g_bb2);
    cudaGetSymbolAddress((void**)&pkb,   g_kb);
    cudaGetSymbolAddress((void**)&pvb,   g_vb);

    cudaFuncSetAttribute(attn_kernel, cudaFuncAttributeMaxDynamicSharedMemorySize, ASM_TOT);
    const int smem_ln = NC * 17 * 4;
    cudaFuncSetAttribute(add_ln_kernel, cudaFuncAttributeMaxDynamicSharedMemorySize, smem_ln);
    const int smem_gemm = 3 * 32768;
    cudaFuncSetAttribute(mma_gemm<3*NC, NC,  1, false, false, true >, cudaFuncAttributeMaxDynamicSharedMemorySize, smem_gemm);
    cudaFuncSetAttribute(mma_gemm<NFC,  NC,  3, true,  true,  false>, cudaFuncAttributeMaxDynamicSharedMemorySize, smem_gemm);
    const int smem_gemm64 = 3 * 24576;
    cudaFuncSetAttribute(mma_gemm_t64<NC, NC,  1>, cudaFuncAttributeMaxDynamicSharedMemorySize, smem_gemm64);
    cudaFuncSetAttribute(mma_gemm_t64<NC, NFC, 3>, cudaFuncAttributeMaxDynamicSharedMemorySize, smem_gemm64);

    {
        int nq = NL*NC*NC;
        convert_small<<<(nq+255)/256, 256>>>(Wq, Wk, Wv, Wo, pwqkv, pwo, nq);
        int tot = NB*NC*NT + NL*3*NC + NB*2*(2*NC) + NB*2*(2*NFC);
        misc_init<<<(tot+255)/256, 256>>>(x, msk, bq, bk, bv);
        im2col_pad<<<dim3(NC/32, NT/32, NB), 256>>>(px, pbb1, NC);
    }

    const dim3 gqkv (3*NC/128, NT/128, NB);
    const dim3 gproj64(NC/128, NT/64,  NB);
    const dim3 gffn1(NFC/128,  NT/128, NB);
    const dim3 gln(NT/16, NB);

    for (int i = 0; i < NL; i++) {
        mma_gemm<3*NC, NC, 1, false, false, true><<<gqkv, 256, smem_gemm>>>(
            pwqkv + (size_t)i*3*NC*NC*3, pbqkv + i*3*NC, pbb1, pq, pkb, pvb);

        attn_kernel<<<dim3(NT/32, NH, NB), 256, ASM_TOT>>>(relk, relv, pbb1);

        mma_gemm_t64<NC, NC, 1><<<gproj64, 256, smem_gemm64>>>(
            pwo + (size_t)i*NC*NC*3, bo + i*NC, pbb1, py);
        add_ln_kernel<<<gln, 256, smem_ln>>>(g1 + i*NC, be1 + i*NC, pbb1, nullptr, nullptr);

        if (i == 0) {
            int n1 = NL*3*NFC*(NC/8);
            convert_w_tap<<<(n1+255)/256, 256>>>(W1, pw1, NFC, NC, n1);
            int n2 = NL*3*NC*(NFC/8);
            convert_w_tap<<<(n2+255)/256, 256>>>(W2, pw2, NC, NFC, n2);
        }

        mma_gemm<NFC, NC, 3, true, true, false><<<gffn1, 256, smem_gemm>>>(
            pw1 + (size_t)i*3*NFC*NC*3, b1 + i*NFC, pbb1, pbb2, nullptr, nullptr);
        mma_gemm_t64<NC, NFC, 3><<<gproj64, 256, smem_gemm64>>>(
            pw2 + (size_t)i*3*NC*NFC*3, b2 + i*NC, pbb2, py);

        if (i == NL - 1) {
            add_ln_kernel<<<gln, 256, smem_ln>>>(g2 + i*NC, be2 + i*NC, pbb1, out, msk);
        } else {
            add_ln_kernel<<<gln, 256, smem_ln>>>(g2 + i*NC, be2 + i*NC, pbb1, nullptr, nullptr);
        }
    }
}

// round 17
// speedup vs baseline: 1.6194x; 1.0584x over previous
#include <cuda_runtime.h>
#include <cuda_bf16.h>
#include <cstdint>
#include <math.h>

#define NB 8
#define NT 512
#define NC 768
#define NFC 3072
#define NH 12
#define NL 6
#define NDK 64
#define Q_SCALE 0.125f
#define NTP (NT + 2)
#define NBH (NB/2)

// ---------------- scratch ----------------
__device__ float g_x  [NB*NC*NT];
__device__ float g_q  [NB*NC*NT];
__device__ float g_y  [NB*NC*NT];
__device__ __nv_bfloat16 g_kb[(size_t)NB*NH*NT*NDK];   // K bf16 [b,h][s][d]
__device__ __nv_bfloat16 g_vb[(size_t)NB*NH*NDK*NT];   // V bf16 [b,h][d][s]

// A weights 3-segment per row: [Wh | Wl | Wh], row len 3*CIN
__device__ __nv_bfloat16 g_wqkv[(size_t)NL*3*NC*NC*3];
__device__ __nv_bfloat16 g_wo  [(size_t)NL*NC*NC*3];
__device__ __nv_bfloat16 g_w1  [(size_t)NL*3*NFC*NC*3];
__device__ __nv_bfloat16 g_w2  [(size_t)NL*3*NC*NFC*3];
__device__ float         g_bqkv[NL*3*NC];
__device__ __nv_bfloat16 g_bb1[(size_t)NB*NTP*NC*2];
__device__ __nv_bfloat16 g_bb2[(size_t)NB*NTP*NFC*2];

__device__ __forceinline__ void split2(float v, __nv_bfloat16& hi, __nv_bfloat16& lo) {
    hi = __float2bfloat16_rn(v);
    lo = __float2bfloat16_rn(v - __bfloat162float(hi));
}

__device__ __forceinline__ float fexp(float x) {
    float y = x * 1.4426950408889634f;
    float n = rintf(y);
    float f = y - n;
    float p = 0.0013333558146428443f;
    p = fmaf(p, f, 0.009618129107628477f);
    p = fmaf(p, f, 0.05550410866482158f);
    p = fmaf(p, f, 0.2402265069591007f);
    p = fmaf(p, f, 0.6931471805599453f);
    p = fmaf(p, f, 1.0f);
    return __int_as_float(__float_as_int(p) + (((int)n) << 23));
}

// ================= conversions =================
__global__ void convert_small(const float* __restrict__ Wq, const float* __restrict__ Wk,
                              const float* __restrict__ Wv, const float* __restrict__ Wo,
                              __nv_bfloat16* __restrict__ oq, __nv_bfloat16* __restrict__ oo, int n) {
    int idx = blockIdx.x * 256 + threadIdx.x;
    if (idx >= n) return;
    int c = idx % NC;
    int m = (idx / NC) % NC;
    int l = idx / (NC * NC);
    const int KPA = 3 * NC;
    float vals[3] = { Wq[idx] * Q_SCALE, Wk[idx], Wv[idx] };
    size_t lb = (size_t)l * (3*NC) * KPA;
    #pragma unroll
    for (int s = 0; s < 3; s++) {
        __nv_bfloat16 hi, lo; split2(vals[s], hi, lo);
        size_t base = lb + (size_t)(s * NC + m) * KPA;
        oq[base + c] = hi; oq[base + NC + c] = lo; oq[base + 2*NC + c] = hi;
    }
    __nv_bfloat16 hi, lo; split2(Wo[idx], hi, lo);
    size_t base = ((size_t)l * NC + m) * KPA;
    oo[base + c] = hi; oo[base + NC + c] = lo; oo[base + 2*NC + c] = hi;
}

__global__ void convert_w_tap(const float* __restrict__ w, __nv_bfloat16* __restrict__ o,
                              int M, int CIN, int n8) {
    int idx = blockIdx.x * 256 + threadIdx.x;
    if (idx >= n8) return;
    int k  = idx % 3;
    int c8 = (idx / 3) % (CIN / 8);
    int m  = (idx / 3 / (CIN / 8)) % M;
    int l  = idx / 3 / (CIN / 8) / M;
    const float* src = w + (((size_t)((size_t)l * M + m) * CIN + c8 * 8) * 3 + k);
    __nv_bfloat16 hb[8], lb[8];
    #pragma unroll
    for (int j = 0; j < 8; j++) split2(src[j * 3], hb[j], lb[j]);
    size_t p = ((size_t)(l * 3 + k) * M + m) * (size_t)(3 * CIN) + c8 * 8;
    *(uint4*)(o + p)           = *(uint4*)hb;
    *(uint4*)(o + p + CIN)     = *(uint4*)lb;
    *(uint4*)(o + p + 2*CIN)   = *(uint4*)hb;
}

__global__ void misc_init(const float* __restrict__ x, const float* __restrict__ msk,
                          const float* __restrict__ bq, const float* __restrict__ bk,
                          const float* __restrict__ bv) {
    int idx = blockIdx.x * 256 + threadIdx.x;
    const int N0 = NB*NC*NT;
    if (idx < N0) {
        int t = idx % NT, b = idx / (NC*NT);
        g_x[idx] = x[idx] * msk[b*NT + t];
        return;
    }
    idx -= N0;
    const int N1 = NL*3*NC;
    if (idx < N1) {
        int j = idx % (3*NC), l = idx / (3*NC);
        g_bqkv[idx] = (j < NC) ? bq[l*NC + j] * Q_SCALE
                    : (j < 2*NC) ? bk[l*NC + j - NC] : bv[l*NC + j - 2*NC];
        return;
    }
    idx -= N1;
    const int N2 = NB*2*(2*NC);
    if (idx < N2) {
        int b = idx / (2*2*NC), r = (idx / (2*NC)) & 1, c = idx % (2*NC);
        g_bb1[((size_t)b*NTP + (r ? NT+1 : 0)) * (2*NC) + c] = __float2bfloat16(0.f);
        return;
    }
    idx -= N2;
    const int N3 = NB*2*(2*NFC);
    if (idx < N3) {
        int b = idx / (2*2*NFC), r = (idx / (2*NFC)) & 1, c = idx % (2*NFC);
        g_bb2[((size_t)b*NTP + (r ? NT+1 : 0)) * (2*NFC) + c] = __float2bfloat16(0.f);
    }
}

__global__ void __launch_bounds__(256) im2col_pad(const float* __restrict__ act,
                                                  __nv_bfloat16* __restrict__ bp, int CIN) {
    __shared__ float tile[32][33];
    const int c0 = blockIdx.x * 32, t00 = blockIdx.y * 32, b = blockIdx.z;
    #pragma unroll
    for (int i = 0; i < 4; i++) {
        int idx = threadIdx.x + i * 256;
        int cl = idx >> 5, tl = idx & 31;
        tile[cl][tl] = act[((size_t)b * CIN + c0 + cl) * NT + t00 + tl];
    }
    __syncthreads();
    #pragma unroll
    for (int i = 0; i < 4; i++) {
        int idx = threadIdx.x + i * 256;
        int tl = idx >> 5, cl = idx & 31;
        __nv_bfloat16 hi, lo; split2(tile[cl][tl], hi, lo);
        size_t row = ((size_t)b * NTP + 1 + t00 + tl) * (2*CIN);
        bp[row + c0 + cl] = hi;
        bp[row + CIN + c0 + cl] = lo;
    }
}

// ================= mma.sync primitives =================
__device__ __forceinline__ uint32_t smem_u32(const void* p) {
    uint32_t a;
    asm("{ .reg .u64 t; cvta.to.shared.u64 t, %1; cvt.u32.u64 %0, t; }" : "=r"(a) : "l"(p));
    return a;
}
#define CP_ASYNC16(dst, src) asm volatile("cp.async.cg.shared.global [%0], [%1], 16;" :: "r"(dst), "l"(src))
#define CP_COMMIT()          asm volatile("cp.async.commit_group;" ::: "memory")
#define CP_WAIT1()           asm volatile("cp.async.wait_group 1;" ::: "memory")
#define CP_WAIT0()           asm volatile("cp.async.wait_group 0;" ::: "memory")

__device__ __forceinline__ void ldsm_x4(uint32_t& r0, uint32_t& r1, uint32_t& r2, uint32_t& r3, uint32_t a) {
    asm volatile("ldmatrix.sync.aligned.m8n8.x4.shared.b16 {%0,%1,%2,%3}, [%4];"
        : "=r"(r0), "=r"(r1), "=r"(r2), "=r"(r3) : "r"(a));
}
__device__ __forceinline__ void mma16816(float* d, uint32_t a0, uint32_t a1, uint32_t a2, uint32_t a3,
                                         uint32_t b0, uint32_t b1) {
    asm volatile("mma.sync.aligned.m16n8k16.row.col.f32.bf16.bf16.f32 "
        "{%0,%1,%2,%3}, {%4,%5,%6,%7}, {%8,%9}, {%0,%1,%2,%3};"
        : "+f"(d[0]), "+f"(d[1]), "+f"(d[2]), "+f"(d[3])
        : "r"(a0), "r"(a1), "r"(a2), "r"(a3), "r"(b0), "r"(b1));
}

// ---------------- 128m x 128t tile (QKV, FFN1) ----------------
template<int MTOT, int CIN, int TAPS, bool RELU, bool BB2, bool QKV>
__global__ void __launch_bounds__(256, 2) mma_gemm(
    const __nv_bfloat16* __restrict__ Aw, const float* __restrict__ bias,
    const __nv_bfloat16* __restrict__ Bb, void* __restrict__ outp,
    __nv_bfloat16* __restrict__ kb, __nv_bfloat16* __restrict__ vb, int b0)
{
    constexpr int KPA = CIN * 3;
    constexpr int KPB = CIN * 2;
    constexpr int NKC = KPA / 64;
    constexpr int TOT = NKC * TAPS;
    constexpr int OFF0 = (TAPS == 1) ? 1 : 0;

    extern __shared__ __align__(1024) char smem[];
    const uint32_t sbase = smem_u32(smem);
    const int tid = threadIdx.x;
    const int wid = tid >> 5, lane = tid & 31;
    const int m0 = blockIdx.x * 128;
    const int t0 = blockIdx.y * 128;
    const int b  = blockIdx.z + b0;

    const __nv_bfloat16* Ag = Aw + (size_t)m0 * KPA;
    const __nv_bfloat16* Bg = Bb + ((size_t)b * NTP + t0 + OFF0) * KPB;

    const int wm = (wid >> 1) * 32;
    const int wn = (wid & 1) * 64;

    float acc[2][8][4];
    #pragma unroll
    for (int i = 0; i < 2; i++)
        #pragma unroll
        for (int j = 0; j < 8; j++)
            #pragma unroll
            for (int q = 0; q < 4; q++) acc[i][j][q] = 0.f;

    auto stage_off = [&](int st) { return sbase + st * 32768u; };

    #define LOAD_STAGE(ST, IC) do { \
        const int _tap = (TAPS == 1) ? 0 : ((IC) / NKC); \
        const int _kc  = ((IC) - _tap * NKC) * 64; \
        const int _bk  = (_kc >= CIN) ? _kc - CIN : _kc; \
        uint32_t sa = stage_off(ST); \
        const __nv_bfloat16* _Asrc = Ag + (size_t)_tap * MTOT * KPA + _kc; \
        const __nv_bfloat16* _Bsrc = Bg + (size_t)_tap * KPB + _bk; \
        _Pragma("unroll") \
        for (int it = 0; it < 8; it++) { \
            int idx = tid + it * 256; \
            if (idx < 1024) { \
                int r = idx >> 3, c = idx & 7; \
                CP_ASYNC16(sa + r * 128 + ((c ^ (r & 7)) * 16), _Asrc + (size_t)r * KPA + c * 8); \
            } else { \
                int j2 = idx - 1024; int r = j2 >> 3, c = j2 & 7; \
                CP_ASYNC16(sa + 16384 + r * 128 + ((c ^ (r & 7)) * 16), _Bsrc + (size_t)r * KPB + c * 8); \
            } \
        } \
    } while (0)

    LOAD_STAGE(0, 0);
    CP_COMMIT();
    LOAD_STAGE(1, 1);
    CP_COMMIT();

    for (int ic = 0; ic < TOT; ic++) {
        CP_WAIT1();
        __syncthreads();
        if (ic + 2 < TOT) {
            int st = (ic + 2) % 3;
            LOAD_STAGE(st, ic + 2);
            CP_COMMIT();
        }

        const uint32_t sA = stage_off(ic % 3);
        const uint32_t sB = sA + 16384;

        #pragma unroll
        for (int k16 = 0; k16 < 4; k16++) {
            uint32_t a[2][4];
            #pragma unroll
            for (int mf = 0; mf < 2; mf++) {
                int r = wm + mf * 16 + (lane & 15);
                int c = k16 * 2 + (lane >> 4);
                ldsm_x4(a[mf][0], a[mf][1], a[mf][2], a[mf][3],
                        sA + r * 128 + ((c ^ (r & 7)) * 16));
            }
            uint32_t bf[8][2];
            #pragma unroll
            for (int nf4 = 0; nf4 < 4; nf4++) {
                int r = wn + nf4 * 16 + (lane & 7) + ((lane >> 4) & 1) * 8;
                int c = k16 * 2 + ((lane >> 3) & 1);
                uint32_t r0, r1, r2, r3;
                ldsm_x4(r0, r1, r2, r3, sB + r * 128 + ((c ^ (r & 7)) * 16));
                bf[nf4*2][0] = r0; bf[nf4*2][1] = r1;
                bf[nf4*2+1][0] = r2; bf[nf4*2+1][1] = r3;
            }
            #pragma unroll
            for (int mf = 0; mf < 2; mf++)
                #pragma unroll
                for (int nf = 0; nf < 8; nf++)
                    mma16816(acc[mf][nf], a[mf][0], a[mf][1], a[mf][2], a[mf][3],
                             bf[nf][0], bf[nf][1]);
        }
    }
    #undef LOAD_STAGE

    const int gr = lane >> 2, qc = lane & 3;
    #pragma unroll
    for (int mf = 0; mf < 2; mf++) {
        int mA = m0 + wm + mf * 16 + gr;
        int mB = mA + 8;
        float bsA = bias[mA], bsB = bias[mB];
        #pragma unroll
        for (int nf = 0; nf < 8; nf++) {
            int tc = wn + nf * 8 + qc * 2;
            float v0 = acc[mf][nf][0] + bsA, v1 = acc[mf][nf][1] + bsA;
            float v2 = acc[mf][nf][2] + bsB, v3 = acc[mf][nf][3] + bsB;
            if (RELU) { v0 = fmaxf(v0,0.f); v1 = fmaxf(v1,0.f); v2 = fmaxf(v2,0.f); v3 = fmaxf(v3,0.f); }
            if (BB2) {
                __nv_bfloat16* bb = (__nv_bfloat16*)outp;
                size_t r0w = ((size_t)b*NTP + 1 + t0 + tc) * (2*MTOT);
                size_t r1w = r0w + (2*MTOT);
                __nv_bfloat16 h, l;
                split2(v0, h, l); bb[r0w + mA] = h; bb[r0w + MTOT + mA] = l;
                split2(v1, h, l); bb[r1w + mA] = h; bb[r1w + MTOT + mA] = l;
                split2(v2, h, l); bb[r0w + mB] = h; bb[r0w + MTOT + mB] = l;
                split2(v3, h, l); bb[r1w + mB] = h; bb[r1w + MTOT + mB] = l;
            } else if (QKV && m0 >= NC) {
                const bool isK = (m0 < 2*NC);
                int moff = mA - (isK ? NC : 2*NC);
                int hh = moff >> 6, dA = moff & 63;
                int st = t0 + tc;
                if (isK) {
                    __nv_bfloat16* kp = kb + ((size_t)b*NH + hh) * NT * NDK;
                    kp[(size_t)st*NDK + dA]         = __float2bfloat16_rn(v0);
                    kp[(size_t)(st+1)*NDK + dA]     = __float2bfloat16_rn(v1);
                    kp[(size_t)st*NDK + dA + 8]     = __float2bfloat16_rn(v2);
                    kp[(size_t)(st+1)*NDK + dA + 8] = __float2bfloat16_rn(v3);
                } else {
                    __nv_bfloat16* vp = vb + ((size_t)b*NH + hh) * NDK * NT;
                    *(__nv_bfloat162*)(vp + (size_t)dA*NT + st)     = __nv_bfloat162{__float2bfloat16_rn(v0), __float2bfloat16_rn(v1)};
                    *(__nv_bfloat162*)(vp + (size_t)(dA+8)*NT + st) = __nv_bfloat162{__float2bfloat16_rn(v2), __float2bfloat16_rn(v3)};
                }
            } else {
                const int MST = QKV ? NC : MTOT;
                float* out = (float*)outp;
                float* rowA = out + ((size_t)b * MST + mA) * NT + t0;
                float* rowB = out + ((size_t)b * MST + mB) * NT + t0;
                *(float2*)(rowA + tc) = make_float2(v0, v1);
                *(float2*)(rowB + tc) = make_float2(v2, v3);
            }
        }
    }
}

// ---------------- 128m x 64t tile, 3 CTAs/SM (O-proj, FFN2) ----------------
template<int MTOT, int CIN, int TAPS>
__global__ void __launch_bounds__(256, 3) mma_gemm_t64(
    const __nv_bfloat16* __restrict__ Aw, const float* __restrict__ bias,
    const __nv_bfloat16* __restrict__ Bb, float* __restrict__ out, int b0)
{
    constexpr int KPA = CIN * 3;
    constexpr int KPB = CIN * 2;
    constexpr int NKC = KPA / 64;
    constexpr int TOT = NKC * TAPS;
    constexpr int OFF0 = (TAPS == 1) ? 1 : 0;

    extern __shared__ __align__(1024) char smem[];
    const uint32_t sbase = smem_u32(smem);
    const int tid = threadIdx.x;
    const int wid = tid >> 5, lane = tid & 31;
    const int m0 = blockIdx.x * 128;
    const int t0 = blockIdx.y * 64;
    const int b  = blockIdx.z + b0;

    const __nv_bfloat16* Ag = Aw + (size_t)m0 * KPA;
    const __nv_bfloat16* Bg = Bb + ((size_t)b * NTP + t0 + OFF0) * KPB;

    const int wm = (wid >> 1) * 32;
    const int wn = (wid & 1) * 32;

    float acc[2][4][4];
    #pragma unroll
    for (int i = 0; i < 2; i++)
        #pragma unroll
        for (int j = 0; j < 4; j++)
            #pragma unroll
            for (int q = 0; q < 4; q++) acc[i][j][q] = 0.f;

    auto stage_off = [&](int st) { return sbase + st * 24576u; };

    #define LOAD_STAGE64(ST, IC) do { \
        const int _tap = (TAPS == 1) ? 0 : ((IC) / NKC); \
        const int _kc  = ((IC) - _tap * NKC) * 64; \
        const int _bk  = (_kc >= CIN) ? _kc - CIN : _kc; \
        uint32_t sa = stage_off(ST); \
        const __nv_bfloat16* _Asrc = Ag + (size_t)_tap * MTOT * KPA + _kc; \
        const __nv_bfloat16* _Bsrc = Bg + (size_t)_tap * KPB + _bk; \
        _Pragma("unroll") \
        for (int it = 0; it < 6; it++) { \
            int idx = tid + it * 256; \
            if (idx < 1024) { \
                int r = idx >> 3, c = idx & 7; \
                CP_ASYNC16(sa + r * 128 + ((c ^ (r & 7)) * 16), _Asrc + (size_t)r * KPA + c * 8); \
            } else { \
                int j2 = idx - 1024; int r = j2 >> 3, c = j2 & 7; \
                CP_ASYNC16(sa + 16384 + r * 128 + ((c ^ (r & 7)) * 16), _Bsrc + (size_t)r * KPB + c * 8); \
            } \
        } \
    } while (0)

    LOAD_STAGE64(0, 0);
    CP_COMMIT();
    LOAD_STAGE64(1, 1);
    CP_COMMIT();

    for (int ic = 0; ic < TOT; ic++) {
        CP_WAIT1();
        __syncthreads();
        if (ic + 2 < TOT) {
            int st = (ic + 2) % 3;
            LOAD_STAGE64(st, ic + 2);
            CP_COMMIT();
        }

        const uint32_t sA = stage_off(ic % 3);
        const uint32_t sB = sA + 16384;

        #pragma unroll
        for (int k16 = 0; k16 < 4; k16++) {
            uint32_t a[2][4];
            #pragma unroll
            for (int mf = 0; mf < 2; mf++) {
                int r = wm + mf * 16 + (lane & 15);
                int c = k16 * 2 + (lane >> 4);
                ldsm_x4(a[mf][0], a[mf][1], a[mf][2], a[mf][3],
                        sA + r * 128 + ((c ^ (r & 7)) * 16));
            }
            uint32_t bf[4][2];
            #pragma unroll
            for (int nf4 = 0; nf4 < 2; nf4++) {
                int r = wn + nf4 * 16 + (lane & 7) + ((lane >> 4) & 1) * 8;
                int c = k16 * 2 + ((lane >> 3) & 1);
                uint32_t r0, r1, r2, r3;
                ldsm_x4(r0, r1, r2, r3, sB + r * 128 + ((c ^ (r & 7)) * 16));
                bf[nf4*2][0] = r0; bf[nf4*2][1] = r1;
                bf[nf4*2+1][0] = r2; bf[nf4*2+1][1] = r3;
            }
            #pragma unroll
            for (int mf = 0; mf < 2; mf++)
                #pragma unroll
                for (int nf = 0; nf < 4; nf++)
                    mma16816(acc[mf][nf], a[mf][0], a[mf][1], a[mf][2], a[mf][3],
                             bf[nf][0], bf[nf][1]);
        }
    }
    #undef LOAD_STAGE64

    const int gr = lane >> 2, qc = lane & 3;
    #pragma unroll
    for (int mf = 0; mf < 2; mf++) {
        int mA = m0 + wm + mf * 16 + gr;
        int mB = mA + 8;
        float bsA = bias[mA], bsB = bias[mB];
        float* rowA = out + ((size_t)b * MTOT + mA) * NT + t0;
        float* rowB = out + ((size_t)b * MTOT + mB) * NT + t0;
        #pragma unroll
        for (int nf = 0; nf < 4; nf++) {
            int tc = wn + nf * 8 + qc * 2;
            *(float2*)(rowA + tc) = make_float2(acc[mf][nf][0] + bsA, acc[mf][nf][1] + bsA);
            *(float2*)(rowB + tc) = make_float2(acc[mf][nf][2] + bsB, acc[mf][nf][3] + bsB);
        }
    }
}

// ================= tensor-core attention (2 CTAs/SM, cp.async K/V) =================
#define ASM_S   0u
#define ASM_KV  66560u
#define ASM_Q   99328u
#define ASM_RQ  107520u
#define ASM_TOT (107520 + 32*12*4)

__global__ void __launch_bounds__(256, 2) attn_kernel(const float* __restrict__ relk,
                                                      const float* __restrict__ relv,
                                                      __nv_bfloat16* __restrict__ bbo, int b0) {
    extern __shared__ __align__(1024) char smraw[];
    const uint32_t sb = smem_u32(smraw);
    float* S  = (float*)(smraw + ASM_S);
    float* rq = (float*)(smraw + ASM_RQ);

    const int tid = threadIdx.x;
    const int wid = tid >> 5, lane = tid & 31;
    const int b = blockIdx.z + b0, h = blockIdx.y;
    const int tq0 = blockIdx.x * 32;
    const float* qg = g_q + ((size_t)b*NC + h*NDK) * NT;
    const __nv_bfloat16* kbp = g_kb + ((size_t)b*NH + h) * NT * NDK;
    const __nv_bfloat16* vbp = g_vb + ((size_t)b*NH + h) * NDK * NT;

    #pragma unroll
    for (int i = 0; i < 8; i++) {
        int idx = tid + i * 256;
        int t = idx & 31, d = idx >> 5;
        float v = qg[(size_t)d*NT + tq0 + t];
        __nv_bfloat16 hi, lo; split2(v, hi, lo);
        uint32_t off = (uint32_t)t*128 + ((((uint32_t)d>>3) ^ (t&7))*16) + (d&7)*2;
        *(__nv_bfloat16*)(smraw + ASM_Q + off)        = hi;
        *(__nv_bfloat16*)(smraw + ASM_Q + 4096 + off) = lo;
    }
    for (int idx = tid; idx < 32*9; idx += 256) {
        int t = idx / 9, dd = idx % 9;
        float s = 0.f;
        #pragma unroll
        for (int d = 0; d < 64; d++) s += qg[(size_t)d*NT + tq0 + t] * relk[dd*64 + d];
        rq[t*12 + dd] = s;
    }
    __syncthreads();

    #pragma unroll
    for (int half = 0; half < 2; half++) {
        #pragma unroll
        for (int i = 0; i < 8; i++) {
            int ch = tid + i * 256;
            int s = ch >> 3, c16 = ch & 7;
            CP_ASYNC16(sb + ASM_KV + (uint32_t)s*128 + (((uint32_t)c16 ^ (s&7))*16),
                       kbp + ((size_t)(half*256 + s))*NDK + c16*8);
        }
        CP_COMMIT(); CP_WAIT0();
        __syncthreads();

        float acc[2][4][4];
        #pragma unroll
        for (int i = 0; i < 2; i++)
            #pragma unroll
            for (int j = 0; j < 4; j++)
                #pragma unroll
                for (int q = 0; q < 4; q++) acc[i][j][q] = 0.f;

        #pragma unroll
        for (int pass = 0; pass < 2; pass++) {
            const uint32_t sA = sb + ASM_Q + pass * 4096;
            #pragma unroll
            for (int k16 = 0; k16 < 4; k16++) {
                uint32_t a[2][4];
                #pragma unroll
                for (int mf = 0; mf < 2; mf++) {
                    int r = mf * 16 + (lane & 15);
                    int c = k16 * 2 + (lane >> 4);
                    ldsm_x4(a[mf][0], a[mf][1], a[mf][2], a[mf][3],
                            sA + r * 128 + ((c ^ (r & 7)) * 16));
                }
                uint32_t bf[4][2];
                #pragma unroll
                for (int nf4 = 0; nf4 < 2; nf4++) {
                    int r = wid * 32 + nf4 * 16 + (lane & 7) + ((lane >> 4) & 1) * 8;
                    int c = k16 * 2 + ((lane >> 3) & 1);
                    uint32_t r0, r1, r2, r3;
                    ldsm_x4(r0, r1, r2, r3, sb + ASM_KV + r * 128 + ((c ^ (r & 7)) * 16));
                    bf[nf4*2][0] = r0; bf[nf4*2][1] = r1;
                    bf[nf4*2+1][0] = r2; bf[nf4*2+1][1] = r3;
                }
                #pragma unroll
                for (int mf = 0; mf < 2; mf++)
                    #pragma unroll
                    for (int nf = 0; nf < 4; nf++)
                        mma16816(acc[mf][nf], a[mf][0], a[mf][1], a[mf][2], a[mf][3],
                                 bf[nf][0], bf[nf][1]);
            }
        }
        const int g = lane >> 2, q = lane & 3;
        #pragma unroll
        for (int mf = 0; mf < 2; mf++)
            #pragma unroll
            for (int nf = 0; nf < 4; nf++) {
                int row = mf * 16 + g;
                int col = half * 256 + wid * 32 + nf * 8 + q * 2;
                S[row*520 + col]       = acc[mf][nf][0];
                S[row*520 + col + 1]   = acc[mf][nf][1];
                S[(row+8)*520 + col]   = acc[mf][nf][2];
                S[(row+8)*520 + col+1] = acc[mf][nf][3];
            }
        __syncthreads();
    }

    for (int idx = tid; idx < 32*9; idx += 256) {
        int t = idx / 9, dd = idx % 9;
        int s = tq0 + t + dd - 4;
        if (s >= 0 && s < NT) S[t*520 + s] += rq[t*12 + dd];
    }
    __syncthreads();
    {
        int r = tid >> 3, l = tid & 7;
        float* row = S + r*520;
        float m = -1e30f;
        for (int j = l; j < NT; j += 8) m = fmaxf(m, row[j]);
        m = fmaxf(m, __shfl_xor_sync(0xffffffffu, m, 1));
        m = fmaxf(m, __shfl_xor_sync(0xffffffffu, m, 2));
        m = fmaxf(m, __shfl_xor_sync(0xffffffffu, m, 4));
        float sum = 0.f;
        for (int j = l; j < NT; j += 8) { float e = fexp(row[j] - m); row[j] = e; sum += e; }
        sum += __shfl_xor_sync(0xffffffffu, sum, 1);
        sum += __shfl_xor_sync(0xffffffffu, sum, 2);
        sum += __shfl_xor_sync(0xffffffffu, sum, 4);
        float inv = 1.f / sum;
        for (int j = l; j < NT; j += 8) row[j] *= inv;
    }
    __syncthreads();

    #pragma unroll
    for (int i = 0; i < 64; i++) {
        int idx = tid + i * 256;
        int s = idx & 511, t = idx >> 9;
        float p = S[t*520 + s];
        int buf = s >> 6, col = s & 63;
        uint32_t off = (uint32_t)buf*4096 + t*128 + ((((uint32_t)col>>3) ^ (t&7))*16) + (col&7)*2;
        *(__nv_bfloat16*)(smraw + ASM_KV + off) = __float2bfloat16_rn(p);
    }
    __syncthreads();

    #pragma unroll
    for (int i = 0; i < 16; i++) {
        int ch = tid + i * 256;
        int c16 = ch & 7, d = (ch >> 3) & 63, buf = ch >> 9;
        CP_ASYNC16(sb + ASM_S + (uint32_t)buf*8192 + (uint32_t)d*128 + (((uint32_t)c16 ^ (d&7))*16),
                   vbp + (size_t)d*NT + buf*64 + c16*8);
    }
    CP_COMMIT(); CP_WAIT0();
    __syncthreads();

    {
        const int kg = wid >> 2;
        const int nw = (wid & 3) * 16;
        float po[2][2][4];
        #pragma unroll
        for (int i = 0; i < 2; i++)
            #pragma unroll
            for (int j = 0; j < 2; j++)
                #pragma unroll
                for (int q = 0; q < 4; q++) po[i][j][q] = 0.f;

        #pragma unroll
        for (int gI = 0; gI < 4; gI++) {
            const uint32_t sA = sb + ASM_KV + (uint32_t)(kg*4 + gI) * 4096;
            const uint32_t sB = sb + ASM_S  + (uint32_t)(kg*4 + gI) * 8192;
            #pragma unroll
            for (int k16 = 0; k16 < 4; k16++) {
                uint32_t a[2][4];
                #pragma unroll
                for (int mf = 0; mf < 2; mf++) {
                    int r = mf * 16 + (lane & 15);
                    int c = k16 * 2 + (lane >> 4);
                    ldsm_x4(a[mf][0], a[mf][1], a[mf][2], a[mf][3],
                            sA + r * 128 + ((c ^ (r & 7)) * 16));
                }
                int r = nw + (lane & 7) + ((lane >> 4) & 1) * 8;
                int c = k16 * 2 + ((lane >> 3) & 1);
                uint32_t r0, r1, r2, r3;
                ldsm_x4(r0, r1, r2, r3, sB + r * 128 + ((c ^ (r & 7)) * 16));
                uint32_t bf[2][2] = {{r0, r1}, {r2, r3}};
                #pragma unroll
                for (int mf = 0; mf < 2; mf++)
                    #pragma unroll
                    for (int nf = 0; nf < 2; nf++)
                        mma16816(po[mf][nf], a[mf][0], a[mf][1], a[mf][2], a[mf][3],
                                 bf[nf][0], bf[nf][1]);
            }
        }

        float* red = (float*)(smraw + ASM_Q);
        const int g = lane >> 2, q = lane & 3;
        if (kg == 1) {
            #pragma unroll
            for (int mf = 0; mf < 2; mf++)
                #pragma unroll
                for (int nf = 0; nf < 2; nf++) {
                    int row = mf * 16 + g;
                    int col = nw + nf * 8 + q * 2;
                    red[row*64 + col]       = po[mf][nf][0];
                    red[row*64 + col + 1]   = po[mf][nf][1];
                    red[(row+8)*64 + col]   = po[mf][nf][2];
                    red[(row+8)*64 + col+1] = po[mf][nf][3];
                }
        }
        __syncthreads();
        if (kg == 0) {
            #pragma unroll
            for (int mf = 0; mf < 2; mf++)
                #pragma unroll
                for (int nf = 0; nf < 2; nf++) {
                    int row = mf * 16 + g;
                    int col = nw + nf * 8 + q * 2;
                    red[row*64 + col]       += po[mf][nf][0];
                    red[row*64 + col + 1]   += po[mf][nf][1];
                    red[(row+8)*64 + col]   += po[mf][nf][2];
                    red[(row+8)*64 + col+1] += po[mf][nf][3];
                }
        }
        __syncthreads();
    }

    {
        float* red = (float*)(smraw + ASM_Q);
        #pragma unroll
        for (int i = 0; i < 8; i++) {
            int idx = tid + i * 256;
            int d = idx & 63, t = idx >> 6;
            float out = red[t*64 + d];
            int tg = tq0 + t;
            #pragma unroll
            for (int dd = 0; dd < 9; dd++) {
                int s = tg + dd - 4;
                if (s >= 0 && s < NT) {
                    int buf = s >> 6, col = s & 63;
                    uint32_t off = (uint32_t)buf*4096 + t*128 + ((((uint32_t)col>>3) ^ (t&7))*16) + (col&7)*2;
                    float p = __bfloat162float(*(__nv_bfloat16*)(smraw + ASM_KV + off));
                    out += p * relv[dd*64 + d];
                }
            }
            __nv_bfloat16 hi, lo; split2(out, hi, lo);
            size_t row = ((size_t)b*NTP + 1 + tg) * (2*NC) + h*NDK;
            bbo[row + d]      = hi;
            bbo[row + NC + d] = lo;
        }
    }
}

// ================= fused residual add + LN (+ bb1 emission | final output) ====
__global__ void __launch_bounds__(256) add_ln_kernel(const float* __restrict__ gam,
                                                     const float* __restrict__ bet,
                                                     __nv_bfloat16* __restrict__ bbo,
                                                     float* __restrict__ finout,
                                                     const float* __restrict__ msk, int b0) {
    extern __shared__ float smv[];
    __shared__ float s_sum[16][16], s_sq[16][16];
    __shared__ float s_mean[16], s_rstd[16];
    const int b  = blockIdx.y + b0;
    const int t0 = blockIdx.x * 16;
    const int l  = threadIdx.x & 15;
    const int cg = threadIdx.x >> 4;

    const float* xb = g_x + (size_t)b*NC*NT + t0 + l;
    const float* yb = g_y + (size_t)b*NC*NT + t0 + l;

    float sum = 0.f, sq = 0.f;
    for (int c = cg; c < NC; c += 16) {
        float v = xb[(size_t)c*NT] + yb[(size_t)c*NT];
        smv[c*17 + l] = v;
        sum += v; sq += v*v;
    }
    s_sum[cg][l] = sum; s_sq[cg][l] = sq;
    __syncthreads();
    if (threadIdx.x < 16) {
        float s = 0.f, q = 0.f;
        #pragma unroll
        for (int g = 0; g < 16; g++) { s += s_sum[g][threadIdx.x]; q += s_sq[g][threadIdx.x]; }
        float mean = s * (1.f/NC);
        float var  = q * (1.f/NC) - mean*mean;
        s_mean[threadIdx.x] = mean;
        s_rstd[threadIdx.x] = rsqrtf(var + 1e-5f);
    }
    __syncthreads();

    if (finout) {
        float mk = msk[b*NT + t0 + l];
        float* oo = finout + (size_t)b*NC*NT + t0 + l;
        for (int c = cg; c < NC; c += 16) {
            float nv = (smv[c*17 + l] - s_mean[l]) * s_rstd[l] * gam[c] + bet[c];
            oo[(size_t)c*NT] = nv * mk;
        }
        return;
    }

    float* xo = g_x + (size_t)b*NC*NT + t0 + l;
    for (int c = cg; c < NC; c += 16) {
        float nv = (smv[c*17 + l] - s_mean[l]) * s_rstd[l] * gam[c] + bet[c];
        xo[(size_t)c*NT] = nv;
        smv[c*17 + l] = nv;
    }
    __syncthreads();
    for (int j = threadIdx.x; j < 16*NC; j += 256) {
        int t = j / NC, c = j - (j / NC) * NC;
        __nv_bfloat16 hi, lo; split2(smv[c*17 + t], hi, lo);
        size_t row = ((size_t)b*NTP + 1 + t0 + t) * (2*NC);
        bbo[row + c] = hi;
        bbo[row + NC + c] = lo;
    }
}

// ================= host =================
extern "C" void kernel_launch(void* const* d_in, const int* in_sizes, int n_in,
                              void* d_out, int out_size) {
    const float* x    = (const float*)d_in[0];
    const float* msk  = (const float*)d_in[1];
    const float* Wq   = (const float*)d_in[2];
    const float* bq   = (const float*)d_in[3];
    const float* Wk   = (const float*)d_in[4];
    const float* bk   = (const float*)d_in[5];
    const float* Wv   = (const float*)d_in[6];
    const float* bv   = (const float*)d_in[7];
    const float* Wo   = (const float*)d_in[8];
    const float* bo   = (const float*)d_in[9];
    const float* relk = (const float*)d_in[10];
    const float* relv = (const float*)d_in[11];
    const float* W1   = (const float*)d_in[12];
    const float* b1   = (const float*)d_in[13];
    const float* W2   = (const float*)d_in[14];
    const float* b2   = (const float*)d_in[15];
    const float* g1   = (const float*)d_in[16];
    const float* be1  = (const float*)d_in[17];
    const float* g2   = (const float*)d_in[18];
    const float* be2  = (const float*)d_in[19];
    float* out = (float*)d_out;

    float *px, *py, *pbqkv, *pq;
    __nv_bfloat16 *pwqkv, *pwo, *pw1, *pw2, *pbb1, *pbb2, *pkb, *pvb;
    cudaGetSymbolAddress((void**)&px,    g_x);
    cudaGetSymbolAddress((void**)&pq,    g_q);
    cudaGetSymbolAddress((void**)&py,    g_y);
    cudaGetSymbolAddress((void**)&pwqkv, g_wqkv);
    cudaGetSymbolAddress((void**)&pwo,   g_wo);
    cudaGetSymbolAddress((void**)&pw1,   g_w1);
    cudaGetSymbolAddress((void**)&pw2,   g_w2);
    cudaGetSymbolAddress((void**)&pbqkv, g_bqkv);
    cudaGetSymbolAddress((void**)&pbb1,  g_bb1);
    cudaGetSymbolAddress((void**)&pbb2,  g_bb2);
    cudaGetSymbolAddress((void**)&pkb,   g_kb);
    cudaGetSymbolAddress((void**)&pvb,   g_vb);

    // one-time stream/event setup (first call is the uncaptured correctness run)
    static cudaStream_t s1 = nullptr;
    static cudaEvent_t evF = nullptr, evJ = nullptr;
    if (!s1) {
        cudaStreamCreateWithFlags(&s1, cudaStreamNonBlocking);
        cudaEventCreateWithFlags(&evF, cudaEventDisableTiming);
        cudaEventCreateWithFlags(&evJ, cudaEventDisableTiming);
    }

    cudaFuncSetAttribute(attn_kernel, cudaFuncAttributeMaxDynamicSharedMemorySize, ASM_TOT);
    const int smem_ln = NC * 17 * 4;
    cudaFuncSetAttribute(add_ln_kernel, cudaFuncAttributeMaxDynamicSharedMemorySize, smem_ln);
    const int smem_gemm = 3 * 32768;
    cudaFuncSetAttribute(mma_gemm<3*NC, NC,  1, false, false, true >, cudaFuncAttributeMaxDynamicSharedMemorySize, smem_gemm);
    cudaFuncSetAttribute(mma_gemm<NFC,  NC,  3, true,  true,  false>, cudaFuncAttributeMaxDynamicSharedMemorySize, smem_gemm);
    const int smem_gemm64 = 3 * 24576;
    cudaFuncSetAttribute(mma_gemm_t64<NC, NC,  1>, cudaFuncAttributeMaxDynamicSharedMemorySize, smem_gemm64);
    cudaFuncSetAttribute(mma_gemm_t64<NC, NFC, 3>, cudaFuncAttributeMaxDynamicSharedMemorySize, smem_gemm64);

    // ---- init phase (all batches, default stream) ----
    {
        int nq = NL*NC*NC;
        convert_small<<<(nq+255)/256, 256>>>(Wq, Wk, Wv, Wo, pwqkv, pwo, nq);
        int n1 = NL*3*NFC*(NC/8);
        convert_w_tap<<<(n1+255)/256, 256>>>(W1, pw1, NFC, NC, n1);
        int n2 = NL*3*NC*(NFC/8);
        convert_w_tap<<<(n2+255)/256, 256>>>(W2, pw2, NC, NFC, n2);
        int tot = NB*NC*NT + NL*3*NC + NB*2*(2*NC) + NB*2*(2*NFC);
        misc_init<<<(tot+255)/256, 256>>>(x, msk, bq, bk, bv);
        im2col_pad<<<dim3(NC/32, NT/32, NB), 256>>>(px, pbb1, NC);
    }

    // ---- fork: half batches on default stream, half on s1 ----
    cudaEventRecord(evF, 0);
    cudaStreamWaitEvent(s1, evF, 0);

    const dim3 gqkv (3*NC/128, NT/128, NBH);
    const dim3 gproj64(NC/128, NT/64,  NBH);
    const dim3 gffn1(NFC/128,  NT/128, NBH);
    const dim3 gattn(NT/32, NH, NBH);
    const dim3 gln(NT/16, NBH);

    cudaStream_t strm[2] = { (cudaStream_t)0, s1 };

    for (int i = 0; i < NL; i++) {
        for (int hf = 0; hf < 2; hf++) {
            cudaStream_t st = strm[hf];
            const int b0 = hf * NBH;

            mma_gemm<3*NC, NC, 1, false, false, true><<<gqkv, 256, smem_gemm, st>>>(
                pwqkv + (size_t)i*3*NC*NC*3, pbqkv + i*3*NC, pbb1, pq, pkb, pvb, b0);

            attn_kernel<<<gattn, 256, ASM_TOT, st>>>(relk, relv, pbb1, b0);

            mma_gemm_t64<NC, NC, 1><<<gproj64, 256, smem_gemm64, st>>>(
                pwo + (size_t)i*NC*NC*3, bo + i*NC, pbb1, py, b0);
            add_ln_kernel<<<gln, 256, smem_ln, st>>>(g1 + i*NC, be1 + i*NC, pbb1, nullptr, nullptr, b0);

            mma_gemm<NFC, NC, 3, true, true, false><<<gffn1, 256, smem_gemm, st>>>(
                pw1 + (size_t)i*3*NFC*NC*3, b1 + i*NFC, pbb1, pbb2, nullptr, nullptr, b0);
            mma_gemm_t64<NC, NFC, 3><<<gproj64, 256, smem_gemm64, st>>>(
                pw2 + (size_t)i*3*NC*NFC*3, b2 + i*NC, pbb2, py, b0);

            if (i == NL - 1) {
                add_ln_kernel<<<gln, 256, smem_ln, st>>>(g2 + i*NC, be2 + i*NC, pbb1, out, msk, b0);
            } else {
                add_ln_kernel<<<gln, 256, smem_ln, st>>>(g2 + i*NC, be2 + i*NC, pbb1, nullptr, nullptr, b0);
            }
        }
    }

    // ---- join ----
    cudaEventRecord(evJ, s1);
    cudaStreamWaitEvent(0, evJ, 0);
}